// round 1
// baseline (speedup 1.0000x reference)
#include <cuda_runtime.h>
#include <math.h>

// ---------------------------------------------------------------------------
// Problem constants
// ---------------------------------------------------------------------------
constexpr int NN  = 20000;     // nodes
constexpr int NE  = 320000;    // edges
constexpr int H   = 256;       // hidden
constexpr int FE  = 64;        // edge feat
constexpr int FV  = 64;        // vertex feat
constexpr int NL  = 4;         // layers
constexpr int FL  = 1024;      // final hidden

// ---------------------------------------------------------------------------
// Scratch (device globals; no dynamic allocation allowed)
// ---------------------------------------------------------------------------
__device__ float g_ein[(size_t)NE * H];     // e_in
__device__ float g_t  [(size_t)NE * H];     // per-layer edge temp
__device__ float g_vin[(size_t)NN * H];     // v_in
__device__ float g_vp [(size_t)NN * H];     // vp
__device__ float g_vie[(size_t)NN * H];     // scatter-max result
__device__ float g_gi [(size_t)NN * 3 * H];
__device__ float g_gh [(size_t)NN * 3 * H];
__device__ float g_hbuf[(size_t)NN * H];
__device__ float g_wcomb[H];
__device__ float g_bcomb[1];
__device__ float g_sum[H];
__device__ float g_sumsq[H];
__device__ float g_scale[H];
__device__ float g_shift[H];

// ---------------------------------------------------------------------------
// Utility: zero a float buffer
// ---------------------------------------------------------------------------
__global__ void zero_k(float* __restrict__ p, int n) {
    int i = blockIdx.x * blockDim.x + threadIdx.x;
    if (i < n) p[i] = 0.0f;
}

// ---------------------------------------------------------------------------
// Fold fin/out linear layers: w_comb[h] = sum_f out_w[f]*fin_w[f,h]
// ---------------------------------------------------------------------------
__global__ void combine_final(const float* __restrict__ fin_w,   // [FL,H]
                              const float* __restrict__ fin_b,   // [FL]
                              const float* __restrict__ out_w,   // [1,FL]
                              const float* __restrict__ out_b) { // [1]
    int h = threadIdx.x;
    float s = 0.0f;
    for (int f = 0; f < FL; f++) s += out_w[f] * fin_w[(size_t)f * H + h];
    g_wcomb[h] = s;
    if (h == 0) {
        float b = out_b[0];
        for (int f = 0; f < FL; f++) b += out_w[f] * fin_b[f];
        g_bcomb[0] = b;
    }
}

// ---------------------------------------------------------------------------
// SGEMM: Y[M,Nc] = X[M,K] @ W[Nc,K]^T + bias[Nc]
// 128x128 tile, BK=16, 256 threads, 8x8 per thread.
// Requires: K % 16 == 0, Nc % 128 == 0. M arbitrary.
// ---------------------------------------------------------------------------
__global__ __launch_bounds__(256, 1)
void gemm_bias(const float* __restrict__ X, const float* __restrict__ W,
               const float* __restrict__ bias, float* __restrict__ Y,
               int M, int Nc, int K) {
    __shared__ float As[16][128];
    __shared__ float Bs[16][128];

    const int tid = threadIdx.x;
    const int bm = blockIdx.y * 128;
    const int bn = blockIdx.x * 128;
    const int tx = tid & 15;        // 0..15 -> N
    const int ty = tid >> 4;        // 0..15 -> M
    const int lr = tid >> 2;        // 0..63 loader row
    const int lc = (tid & 3) << 2;  // 0,4,8,12 loader col

    float acc[8][8];
#pragma unroll
    for (int i = 0; i < 8; i++)
#pragma unroll
        for (int j = 0; j < 8; j++) acc[i][j] = 0.0f;

    for (int k0 = 0; k0 < K; k0 += 16) {
#pragma unroll
        for (int i = 0; i < 2; i++) {
            int row = bm + lr + i * 64;
            float4 v = make_float4(0.f, 0.f, 0.f, 0.f);
            if (row < M) v = *(const float4*)(X + (size_t)row * K + k0 + lc);
            As[lc + 0][lr + i * 64] = v.x;
            As[lc + 1][lr + i * 64] = v.y;
            As[lc + 2][lr + i * 64] = v.z;
            As[lc + 3][lr + i * 64] = v.w;
        }
#pragma unroll
        for (int i = 0; i < 2; i++) {
            int row = bn + lr + i * 64;   // Nc % 128 == 0 -> always valid
            float4 v = *(const float4*)(W + (size_t)row * K + k0 + lc);
            Bs[lc + 0][lr + i * 64] = v.x;
            Bs[lc + 1][lr + i * 64] = v.y;
            Bs[lc + 2][lr + i * 64] = v.z;
            Bs[lc + 3][lr + i * 64] = v.w;
        }
        __syncthreads();

#pragma unroll
        for (int k = 0; k < 16; k++) {
            float a[8], b[8];
            float4 a0 = *(float4*)&As[k][ty * 8];
            float4 a1 = *(float4*)&As[k][ty * 8 + 4];
            float4 b0 = *(float4*)&Bs[k][tx * 8];
            float4 b1 = *(float4*)&Bs[k][tx * 8 + 4];
            a[0]=a0.x; a[1]=a0.y; a[2]=a0.z; a[3]=a0.w;
            a[4]=a1.x; a[5]=a1.y; a[6]=a1.z; a[7]=a1.w;
            b[0]=b0.x; b[1]=b0.y; b[2]=b0.z; b[3]=b0.w;
            b[4]=b1.x; b[5]=b1.y; b[6]=b1.z; b[7]=b1.w;
#pragma unroll
            for (int i = 0; i < 8; i++)
#pragma unroll
                for (int j = 0; j < 8; j++) acc[i][j] = fmaf(a[i], b[j], acc[i][j]);
        }
        __syncthreads();
    }

    float4 bb0 = *(const float4*)&bias[bn + tx * 8];
    float4 bb1 = *(const float4*)&bias[bn + tx * 8 + 4];
    float bv[8] = {bb0.x, bb0.y, bb0.z, bb0.w, bb1.x, bb1.y, bb1.z, bb1.w};

#pragma unroll
    for (int i = 0; i < 8; i++) {
        int row = bm + ty * 8 + i;
        if (row < M) {
            float4 o0 = make_float4(acc[i][0] + bv[0], acc[i][1] + bv[1],
                                    acc[i][2] + bv[2], acc[i][3] + bv[3]);
            float4 o1 = make_float4(acc[i][4] + bv[4], acc[i][5] + bv[5],
                                    acc[i][6] + bv[6], acc[i][7] + bv[7]);
            *(float4*)(Y + (size_t)row * Nc + bn + tx * 8)     = o0;
            *(float4*)(Y + (size_t)row * Nc + bn + tx * 8 + 4) = o1;
        }
    }
}

// ---------------------------------------------------------------------------
// t[e,h] += vp[src[e],h] + vp[dst[e],h]; accumulate BN stats (sum, sumsq)
// One block = 256 threads (h = threadIdx.x), rows chunked by block.
// ---------------------------------------------------------------------------
__global__ void edge_pre_bn(float* __restrict__ t, const float* __restrict__ vp,
                            const int* __restrict__ src, const int* __restrict__ dst,
                            int E) {
    int h = threadIdx.x;
    int rowsPer = (E + gridDim.x - 1) / gridDim.x;
    int r0 = blockIdx.x * rowsPer;
    int r1 = min(r0 + rowsPer, E);
    float s = 0.f, s2 = 0.f;
    for (int r = r0; r < r1; r++) {
        int a = src[r], b = dst[r];
        float v = t[(size_t)r * H + h] + vp[(size_t)a * H + h] + vp[(size_t)b * H + h];
        t[(size_t)r * H + h] = v;
        s += v;
        s2 += v * v;
    }
    atomicAdd(&g_sum[h], s);
    atomicAdd(&g_sumsq[h], s2);
}

// ---------------------------------------------------------------------------
// Finalize BN: scale/shift per channel (biased variance, eps=1e-5)
// ---------------------------------------------------------------------------
__global__ void bn_finalize(const float* __restrict__ g, const float* __restrict__ b,
                            float inv_n) {
    int h = threadIdx.x;
    float mean = g_sum[h] * inv_n;
    float var = g_sumsq[h] * inv_n - mean * mean;
    float sc = g[h] * rsqrtf(var + 1e-5f);
    g_scale[h] = sc;
    g_shift[h] = b[h] - mean * sc;
}

// ---------------------------------------------------------------------------
// ep = relu(bn(t)); scatter-max into vie[src], vie[dst]; e_in += ep
// (atomicMax on int works since ep >= 0 and vie zero-initialized)
// ---------------------------------------------------------------------------
__global__ void bn_relu_scatter(const float* __restrict__ t, float* __restrict__ ein,
                                float* __restrict__ vie, const int* __restrict__ src,
                                const int* __restrict__ dst, int E) {
    size_t total = (size_t)E * H;
    size_t stride = (size_t)gridDim.x * blockDim.x;
    for (size_t idx = (size_t)blockIdx.x * blockDim.x + threadIdx.x; idx < total;
         idx += stride) {
        int h = (int)(idx & (H - 1));
        int r = (int)(idx >> 8);
        float v = fmaf(t[idx], g_scale[h], g_shift[h]);
        v = fmaxf(v, 0.0f);
        int a = src[r], b = dst[r];
        atomicMax((int*)&vie[(size_t)a * H + h], __float_as_int(v));
        atomicMax((int*)&vie[(size_t)b * H + h], __float_as_int(v));
        ein[idx] += v;
    }
}

// ---------------------------------------------------------------------------
// GRU gate math + BN stats on h. Stride is a multiple of 256 so the channel
// (idx & 255) is constant per thread -> per-thread partial stats.
// ---------------------------------------------------------------------------
__global__ void gru_elem(const float* __restrict__ gi, const float* __restrict__ gh,
                         const float* __restrict__ vin, float* __restrict__ hbuf,
                         int N) {
    size_t total = (size_t)N * H;
    size_t stride = (size_t)gridDim.x * blockDim.x;   // multiple of 256
    int h = threadIdx.x & (H - 1);
    float s = 0.f, s2 = 0.f;
    bool any = false;
    for (size_t idx = (size_t)blockIdx.x * blockDim.x + threadIdx.x; idx < total;
         idx += stride) {
        int n = (int)(idx >> 8);
        const float* giR = gi + (size_t)n * (3 * H);
        const float* ghR = gh + (size_t)n * (3 * H);
        float ir = giR[h], iz = giR[h + H], ig = giR[h + 2 * H];
        float hr = ghR[h], hz = ghR[h + H], hg = ghR[h + 2 * H];
        float r = 1.0f / (1.0f + expf(-(ir + hr)));
        float z = 1.0f / (1.0f + expf(-(iz + hz)));
        float nn = tanhf(ig + r * hg);
        float hv = (1.0f - z) * nn + z * vin[idx];
        hbuf[idx] = hv;
        s += hv;
        s2 += hv * hv;
        any = true;
    }
    if (any) {
        atomicAdd(&g_sum[h], s);
        atomicAdd(&g_sumsq[h], s2);
    }
}

// ---------------------------------------------------------------------------
// v_in += relu(bn(hbuf))
// ---------------------------------------------------------------------------
__global__ void v_update(float* __restrict__ vin, const float* __restrict__ hbuf,
                         int total) {
    int stride = gridDim.x * blockDim.x;
    for (int idx = blockIdx.x * blockDim.x + threadIdx.x; idx < total; idx += stride) {
        int h = idx & (H - 1);
        float v = fmaf(hbuf[idx], g_scale[h], g_shift[h]);
        vin[idx] += fmaxf(v, 0.0f);
    }
}

// ---------------------------------------------------------------------------
// out[e] = dot(e_in[e], w_comb) + b_comb   (one warp per edge)
// ---------------------------------------------------------------------------
__global__ void final_out(const float* __restrict__ ein, float* __restrict__ out,
                          int E) {
    int warp = (blockIdx.x * blockDim.x + threadIdx.x) >> 5;
    int lane = threadIdx.x & 31;
    if (warp >= E) return;
    const float* row = ein + (size_t)warp * H;
    float s = 0.f;
#pragma unroll
    for (int j = 0; j < 8; j++) {
        int c = j * 32 + lane;
        s = fmaf(row[c], g_wcomb[c], s);
    }
#pragma unroll
    for (int o = 16; o > 0; o >>= 1) s += __shfl_xor_sync(0xFFFFFFFFu, s, o);
    if (lane == 0) out[warp] = s + g_bcomb[0];
}

// ---------------------------------------------------------------------------
// Launch
// ---------------------------------------------------------------------------
extern "C" void kernel_launch(void* const* d_in, const int* in_sizes, int n_in,
                              void* d_out, int out_size) {
    const float* x         = (const float*)d_in[0];
    const float* edge_attr = (const float*)d_in[1];
    const int*   edge_idx  = (const int*)  d_in[2];
    const float* ew        = (const float*)d_in[3];
    const float* eb        = (const float*)d_in[4];
    const float* vw        = (const float*)d_in[5];
    const float* vb        = (const float*)d_in[6];
    const float* Le_w      = (const float*)d_in[7];
    const float* Le_b      = (const float*)d_in[8];
    const float* Lv_w      = (const float*)d_in[9];
    const float* Lv_b      = (const float*)d_in[10];
    const float* bne_g     = (const float*)d_in[11];
    const float* bne_b     = (const float*)d_in[12];
    const float* bnv_g     = (const float*)d_in[13];
    const float* bnv_b     = (const float*)d_in[14];
    const float* gru_wih   = (const float*)d_in[15];
    const float* gru_whh   = (const float*)d_in[16];
    const float* gru_bih   = (const float*)d_in[17];
    const float* gru_bhh   = (const float*)d_in[18];
    const float* fin_w     = (const float*)d_in[19];
    const float* fin_b     = (const float*)d_in[20];
    const float* out_w     = (const float*)d_in[21];
    const float* out_b     = (const float*)d_in[22];
    float* out = (float*)d_out;

    const int E = in_sizes[1] / FE;
    const int N = in_sizes[0] / FV;
    const int* src = edge_idx;
    const int* dst = edge_idx + E;

    float *p_ein, *p_t, *p_vin, *p_vp, *p_vie, *p_gi, *p_gh, *p_hbuf, *p_sum, *p_sumsq;
    cudaGetSymbolAddress((void**)&p_ein,  g_ein);
    cudaGetSymbolAddress((void**)&p_t,    g_t);
    cudaGetSymbolAddress((void**)&p_vin,  g_vin);
    cudaGetSymbolAddress((void**)&p_vp,   g_vp);
    cudaGetSymbolAddress((void**)&p_vie,  g_vie);
    cudaGetSymbolAddress((void**)&p_gi,   g_gi);
    cudaGetSymbolAddress((void**)&p_gh,   g_gh);
    cudaGetSymbolAddress((void**)&p_hbuf, g_hbuf);
    cudaGetSymbolAddress((void**)&p_sum,  g_sum);
    cudaGetSymbolAddress((void**)&p_sumsq,g_sumsq);

    const int nbE = (E + 127) / 128;   // 2500
    const int nbN = (N + 127) / 128;   // 157

    // fold fin/out linear tail into a single [H] vector
    combine_final<<<1, H>>>(fin_w, fin_b, out_w, out_b);

    // encoders
    gemm_bias<<<dim3(H / 128, nbE), 256>>>(edge_attr, ew, eb, p_ein, E, H, FE);
    gemm_bias<<<dim3(H / 128, nbN), 256>>>(x, vw, vb, p_vin, N, H, FV);

    for (int k = 0; k < NL; k++) {
        // vp = v_in @ Lv_w^T + Lv_b ; e = e_in @ Le_w^T + Le_b
        gemm_bias<<<dim3(H / 128, nbN), 256>>>(p_vin, Lv_w + (size_t)k * H * H,
                                               Lv_b + k * H, p_vp, N, H, H);
        gemm_bias<<<dim3(H / 128, nbE), 256>>>(p_ein, Le_w + (size_t)k * H * H,
                                               Le_b + k * H, p_t, E, H, H);

        // BN-e stats (fused with +vp[src]+vp[dst])
        zero_k<<<1, 256>>>(p_sum, H);
        zero_k<<<1, 256>>>(p_sumsq, H);
        edge_pre_bn<<<2048, 256>>>(p_t, p_vp, src, dst, E);
        bn_finalize<<<1, H>>>(bne_g + k * H, bne_b + k * H, 1.0f / (float)E);

        // scatter-max + e_in residual
        zero_k<<<(N * H + 255) / 256, 256>>>(p_vie, N * H);
        bn_relu_scatter<<<4096, 256>>>(p_t, p_ein, p_vie, src, dst, E);

        // GRU
        gemm_bias<<<dim3(3 * H / 128, nbN), 256>>>(p_vie, gru_wih + (size_t)k * 3 * H * H,
                                                   gru_bih + (size_t)k * 3 * H, p_gi,
                                                   N, 3 * H, H);
        gemm_bias<<<dim3(3 * H / 128, nbN), 256>>>(p_vin, gru_whh + (size_t)k * 3 * H * H,
                                                   gru_bhh + (size_t)k * 3 * H, p_gh,
                                                   N, 3 * H, H);
        zero_k<<<1, 256>>>(p_sum, H);
        zero_k<<<1, 256>>>(p_sumsq, H);
        gru_elem<<<512, 256>>>(p_gi, p_gh, p_vin, p_hbuf, N);
        bn_finalize<<<1, H>>>(bnv_g + k * H, bnv_b + k * H, 1.0f / (float)N);
        v_update<<<2048, 256>>>(p_vin, p_hbuf, N * H);
    }

    // out[e] = dot(e_in[e], w_comb) + b_comb
    final_out<<<(E * 32 + 255) / 256, 256>>>(p_ein, out, E);
}

// round 2
// speedup vs baseline: 1.9242x; 1.9242x over previous
#include <cuda_runtime.h>
#include <math.h>
#include <stdint.h>

// ---------------------------------------------------------------------------
// Problem constants
// ---------------------------------------------------------------------------
constexpr int NN  = 20000;     // nodes
constexpr int NE  = 320000;    // edges
constexpr int H   = 256;       // hidden
constexpr int FE  = 64;        // edge feat
constexpr int FV  = 64;        // vertex feat
constexpr int NL  = 4;         // layers
constexpr int FL  = 1024;      // final hidden

// ---------------------------------------------------------------------------
// Scratch (device globals; no dynamic allocation allowed)
// ---------------------------------------------------------------------------
__device__ float g_ein[(size_t)NE * H];     // e_in
__device__ float g_t  [(size_t)NE * H];     // per-layer edge temp
__device__ float g_vin[(size_t)NN * H];     // v_in
__device__ float g_vp [(size_t)NN * H];     // vp
__device__ float g_vie[(size_t)NN * H];     // scatter-max result
__device__ float g_gi [(size_t)NN * 3 * H];
__device__ float g_gh [(size_t)NN * 3 * H];
__device__ float g_hbuf[(size_t)NN * H];
__device__ float g_wcomb[H];
__device__ float g_bcomb[1];
__device__ float g_sum[H];
__device__ float g_sumsq[H];
__device__ float g_scale[H];
__device__ float g_shift[H];

// ---------------------------------------------------------------------------
// Utility: zero a float buffer
// ---------------------------------------------------------------------------
__global__ void zero_k(float* __restrict__ p, int n) {
    int i = blockIdx.x * blockDim.x + threadIdx.x;
    if (i < n) p[i] = 0.0f;
}

// ---------------------------------------------------------------------------
// Fold fin/out linear layers: w_comb[h] = sum_f out_w[f]*fin_w[f,h]
// ---------------------------------------------------------------------------
__global__ void combine_final(const float* __restrict__ fin_w,   // [FL,H]
                              const float* __restrict__ fin_b,   // [FL]
                              const float* __restrict__ out_w,   // [1,FL]
                              const float* __restrict__ out_b) { // [1]
    int h = threadIdx.x;
    float s = 0.0f;
    for (int f = 0; f < FL; f++) s += out_w[f] * fin_w[(size_t)f * H + h];
    g_wcomb[h] = s;
    if (h == 0) {
        float b = out_b[0];
        for (int f = 0; f < FL; f++) b += out_w[f] * fin_b[f];
        g_bcomb[0] = b;
    }
}

// ---------------------------------------------------------------------------
// TF32 tensor-core GEMM: Y[M,Nc] = X[M,K] @ W[Nc,K]^T + bias[Nc]
// 128x128 block tile, BK=16, 256 threads = 8 warps (2x4), warp tile 64x32.
// mma.sync.m16n8k8 tf32 with fp32 accumulation, cp.async double buffer.
// Requires: K % 16 == 0, Nc % 128 == 0. M arbitrary.
// Smem stride = 20 floats: bank = (20*row + k) % 32 is conflict-free for the
// tf32 fragment pattern (row = lane>>2, k = lane&3 (+4)).
// ---------------------------------------------------------------------------
#define SM_STRIDE 20

__device__ __forceinline__ void cp_async16(uint32_t smem, const void* gmem, int sz) {
    asm volatile("cp.async.cg.shared.global [%0], [%1], 16, %2;\n"
                 :: "r"(smem), "l"(gmem), "r"(sz));
}
__device__ __forceinline__ void cp_commit() { asm volatile("cp.async.commit_group;\n"); }
__device__ __forceinline__ void cp_wait0()  { asm volatile("cp.async.wait_group 0;\n"); }
__device__ __forceinline__ uint32_t f2tf32(float f) {
    uint32_t u;
    asm("cvt.rna.tf32.f32 %0, %1;\n" : "=r"(u) : "f"(f));
    return u;
}

__global__ __launch_bounds__(256)
void gemm_tf32(const float* __restrict__ X, const float* __restrict__ W,
               const float* __restrict__ bias, float* __restrict__ Y,
               int M, int Nc, int K) {
    __shared__ float As[2][128 * SM_STRIDE];
    __shared__ float Bs[2][128 * SM_STRIDE];

    const int tid  = threadIdx.x;
    const int lane = tid & 31;
    const int warp = tid >> 5;
    const int wm   = (warp >> 2) * 64;   // warp row offset (0,64)
    const int wn   = (warp & 3) * 32;    // warp col offset (0,32,64,96)
    const int bm   = blockIdx.y * 128;
    const int bn   = blockIdx.x * 128;

    float acc[4][4][4];
#pragma unroll
    for (int i = 0; i < 4; i++)
#pragma unroll
        for (int j = 0; j < 4; j++)
#pragma unroll
            for (int c = 0; c < 4; c++) acc[i][j][c] = 0.0f;

    const int KT = K >> 4;   // BK = 16

    // loader mapping: 512 float4 per tile per matrix; 2 per thread.
    // id = tid + i*256, row = id>>2 (0..127), c4 = (id&3)*4.
    auto load_tile = [&](int buf, int kt) {
#pragma unroll
        for (int i = 0; i < 2; i++) {
            int id  = tid + i * 256;
            int row = id >> 2;
            int c4  = (id & 3) << 2;
            // A
            int ar = bm + row;
            int ok = (ar < M) ? 16 : 0;
            int arc = (ar < M) ? ar : (M - 1);
            uint32_t sa = (uint32_t)__cvta_generic_to_shared(
                &As[buf][row * SM_STRIDE + c4]);
            cp_async16(sa, X + (size_t)arc * K + kt * 16 + c4, ok);
            // B (always in-bounds: Nc % 128 == 0)
            int br = bn + row;
            uint32_t sb = (uint32_t)__cvta_generic_to_shared(
                &Bs[buf][row * SM_STRIDE + c4]);
            cp_async16(sb, W + (size_t)br * K + kt * 16 + c4, 16);
        }
        cp_commit();
    };

    load_tile(0, 0);
    int buf = 0;

    for (int kt = 0; kt < KT; kt++) {
        cp_wait0();
        __syncthreads();
        if (kt + 1 < KT) load_tile(buf ^ 1, kt + 1);

#pragma unroll
        for (int ks = 0; ks < 2; ks++) {
            const int kb = ks * 8 + (lane & 3);
            uint32_t a[4][4], b[4][2];
#pragma unroll
            for (int mf = 0; mf < 4; mf++) {
                int r0 = wm + mf * 16 + (lane >> 2);
                a[mf][0] = f2tf32(As[buf][r0 * SM_STRIDE + kb]);
                a[mf][1] = f2tf32(As[buf][(r0 + 8) * SM_STRIDE + kb]);
                a[mf][2] = f2tf32(As[buf][r0 * SM_STRIDE + kb + 4]);
                a[mf][3] = f2tf32(As[buf][(r0 + 8) * SM_STRIDE + kb + 4]);
            }
#pragma unroll
            for (int nf = 0; nf < 4; nf++) {
                int cc = wn + nf * 8 + (lane >> 2);
                b[nf][0] = f2tf32(Bs[buf][cc * SM_STRIDE + kb]);
                b[nf][1] = f2tf32(Bs[buf][cc * SM_STRIDE + kb + 4]);
            }
#pragma unroll
            for (int mf = 0; mf < 4; mf++)
#pragma unroll
                for (int nf = 0; nf < 4; nf++) {
                    asm volatile(
                        "mma.sync.aligned.m16n8k8.row.col.f32.tf32.tf32.f32 "
                        "{%0,%1,%2,%3},{%4,%5,%6,%7},{%8,%9},{%0,%1,%2,%3};\n"
                        : "+f"(acc[mf][nf][0]), "+f"(acc[mf][nf][1]),
                          "+f"(acc[mf][nf][2]), "+f"(acc[mf][nf][3])
                        : "r"(a[mf][0]), "r"(a[mf][1]), "r"(a[mf][2]), "r"(a[mf][3]),
                          "r"(b[nf][0]), "r"(b[nf][1]));
                }
        }
        __syncthreads();
        buf ^= 1;
    }

    // Epilogue: += bias, store float2
#pragma unroll
    for (int nf = 0; nf < 4; nf++) {
        int col = bn + wn + nf * 8 + (lane & 3) * 2;
        float b0 = bias[col], b1 = bias[col + 1];
#pragma unroll
        for (int mf = 0; mf < 4; mf++) {
            int row = bm + wm + mf * 16 + (lane >> 2);
            if (row < M) {
                float2 o = make_float2(acc[mf][nf][0] + b0, acc[mf][nf][1] + b1);
                *(float2*)(Y + (size_t)row * Nc + col) = o;
            }
            if (row + 8 < M) {
                float2 o = make_float2(acc[mf][nf][2] + b0, acc[mf][nf][3] + b1);
                *(float2*)(Y + (size_t)(row + 8) * Nc + col) = o;
            }
        }
    }
}

// ---------------------------------------------------------------------------
// t[e,h] += vp[src[e],h] + vp[dst[e],h]; accumulate BN stats (sum, sumsq)
// ---------------------------------------------------------------------------
__global__ void edge_pre_bn(float* __restrict__ t, const float* __restrict__ vp,
                            const int* __restrict__ src, const int* __restrict__ dst,
                            int E) {
    int h = threadIdx.x;
    int rowsPer = (E + gridDim.x - 1) / gridDim.x;
    int r0 = blockIdx.x * rowsPer;
    int r1 = min(r0 + rowsPer, E);
    float s = 0.f, s2 = 0.f;
    for (int r = r0; r < r1; r++) {
        int a = src[r], b = dst[r];
        float v = t[(size_t)r * H + h] + vp[(size_t)a * H + h] + vp[(size_t)b * H + h];
        t[(size_t)r * H + h] = v;
        s += v;
        s2 += v * v;
    }
    atomicAdd(&g_sum[h], s);
    atomicAdd(&g_sumsq[h], s2);
}

// ---------------------------------------------------------------------------
// Finalize BN: scale/shift per channel (biased variance, eps=1e-5)
// ---------------------------------------------------------------------------
__global__ void bn_finalize(const float* __restrict__ g, const float* __restrict__ b,
                            float inv_n) {
    int h = threadIdx.x;
    float mean = g_sum[h] * inv_n;
    float var = g_sumsq[h] * inv_n - mean * mean;
    float sc = g[h] * rsqrtf(var + 1e-5f);
    g_scale[h] = sc;
    g_shift[h] = b[h] - mean * sc;
}

// ---------------------------------------------------------------------------
// ep = relu(bn(t)); scatter-max into vie[src], vie[dst]; e_in += ep
// ---------------------------------------------------------------------------
__global__ void bn_relu_scatter(const float* __restrict__ t, float* __restrict__ ein,
                                float* __restrict__ vie, const int* __restrict__ src,
                                const int* __restrict__ dst, int E) {
    size_t total = (size_t)E * H;
    size_t stride = (size_t)gridDim.x * blockDim.x;
    for (size_t idx = (size_t)blockIdx.x * blockDim.x + threadIdx.x; idx < total;
         idx += stride) {
        int h = (int)(idx & (H - 1));
        int r = (int)(idx >> 8);
        float v = fmaf(t[idx], g_scale[h], g_shift[h]);
        v = fmaxf(v, 0.0f);
        int a = src[r], b = dst[r];
        atomicMax((int*)&vie[(size_t)a * H + h], __float_as_int(v));
        atomicMax((int*)&vie[(size_t)b * H + h], __float_as_int(v));
        ein[idx] += v;
    }
}

// ---------------------------------------------------------------------------
// GRU gate math + BN stats on h.
// ---------------------------------------------------------------------------
__global__ void gru_elem(const float* __restrict__ gi, const float* __restrict__ gh,
                         const float* __restrict__ vin, float* __restrict__ hbuf,
                         int N) {
    size_t total = (size_t)N * H;
    size_t stride = (size_t)gridDim.x * blockDim.x;   // multiple of 256
    int h = threadIdx.x & (H - 1);
    float s = 0.f, s2 = 0.f;
    bool any = false;
    for (size_t idx = (size_t)blockIdx.x * blockDim.x + threadIdx.x; idx < total;
         idx += stride) {
        int n = (int)(idx >> 8);
        const float* giR = gi + (size_t)n * (3 * H);
        const float* ghR = gh + (size_t)n * (3 * H);
        float ir = giR[h], iz = giR[h + H], ig = giR[h + 2 * H];
        float hr = ghR[h], hz = ghR[h + H], hg = ghR[h + 2 * H];
        float r = 1.0f / (1.0f + expf(-(ir + hr)));
        float z = 1.0f / (1.0f + expf(-(iz + hz)));
        float nn = tanhf(ig + r * hg);
        float hv = (1.0f - z) * nn + z * vin[idx];
        hbuf[idx] = hv;
        s += hv;
        s2 += hv * hv;
        any = true;
    }
    if (any) {
        atomicAdd(&g_sum[h], s);
        atomicAdd(&g_sumsq[h], s2);
    }
}

// ---------------------------------------------------------------------------
// v_in += relu(bn(hbuf))
// ---------------------------------------------------------------------------
__global__ void v_update(float* __restrict__ vin, const float* __restrict__ hbuf,
                         int total) {
    int stride = gridDim.x * blockDim.x;
    for (int idx = blockIdx.x * blockDim.x + threadIdx.x; idx < total; idx += stride) {
        int h = idx & (H - 1);
        float v = fmaf(hbuf[idx], g_scale[h], g_shift[h]);
        vin[idx] += fmaxf(v, 0.0f);
    }
}

// ---------------------------------------------------------------------------
// out[e] = dot(e_in[e], w_comb) + b_comb   (one warp per edge)
// ---------------------------------------------------------------------------
__global__ void final_out(const float* __restrict__ ein, float* __restrict__ out,
                          int E) {
    int warp = (blockIdx.x * blockDim.x + threadIdx.x) >> 5;
    int lane = threadIdx.x & 31;
    if (warp >= E) return;
    const float* row = ein + (size_t)warp * H;
    float s = 0.f;
#pragma unroll
    for (int j = 0; j < 8; j++) {
        int c = j * 32 + lane;
        s = fmaf(row[c], g_wcomb[c], s);
    }
#pragma unroll
    for (int o = 16; o > 0; o >>= 1) s += __shfl_xor_sync(0xFFFFFFFFu, s, o);
    if (lane == 0) out[warp] = s + g_bcomb[0];
}

// ---------------------------------------------------------------------------
// Launch
// ---------------------------------------------------------------------------
extern "C" void kernel_launch(void* const* d_in, const int* in_sizes, int n_in,
                              void* d_out, int out_size) {
    const float* x         = (const float*)d_in[0];
    const float* edge_attr = (const float*)d_in[1];
    const int*   edge_idx  = (const int*)  d_in[2];
    const float* ew        = (const float*)d_in[3];
    const float* eb        = (const float*)d_in[4];
    const float* vw        = (const float*)d_in[5];
    const float* vb        = (const float*)d_in[6];
    const float* Le_w      = (const float*)d_in[7];
    const float* Le_b      = (const float*)d_in[8];
    const float* Lv_w      = (const float*)d_in[9];
    const float* Lv_b      = (const float*)d_in[10];
    const float* bne_g     = (const float*)d_in[11];
    const float* bne_b     = (const float*)d_in[12];
    const float* bnv_g     = (const float*)d_in[13];
    const float* bnv_b     = (const float*)d_in[14];
    const float* gru_wih   = (const float*)d_in[15];
    const float* gru_whh   = (const float*)d_in[16];
    const float* gru_bih   = (const float*)d_in[17];
    const float* gru_bhh   = (const float*)d_in[18];
    const float* fin_w     = (const float*)d_in[19];
    const float* fin_b     = (const float*)d_in[20];
    const float* out_w     = (const float*)d_in[21];
    const float* out_b     = (const float*)d_in[22];
    float* out = (float*)d_out;

    const int E = in_sizes[1] / FE;
    const int N = in_sizes[0] / FV;
    const int* src = edge_idx;
    const int* dst = edge_idx + E;

    float *p_ein, *p_t, *p_vin, *p_vp, *p_vie, *p_gi, *p_gh, *p_hbuf, *p_sum, *p_sumsq;
    cudaGetSymbolAddress((void**)&p_ein,  g_ein);
    cudaGetSymbolAddress((void**)&p_t,    g_t);
    cudaGetSymbolAddress((void**)&p_vin,  g_vin);
    cudaGetSymbolAddress((void**)&p_vp,   g_vp);
    cudaGetSymbolAddress((void**)&p_vie,  g_vie);
    cudaGetSymbolAddress((void**)&p_gi,   g_gi);
    cudaGetSymbolAddress((void**)&p_gh,   g_gh);
    cudaGetSymbolAddress((void**)&p_hbuf, g_hbuf);
    cudaGetSymbolAddress((void**)&p_sum,  g_sum);
    cudaGetSymbolAddress((void**)&p_sumsq,g_sumsq);

    const int nbE = (E + 127) / 128;   // 2500
    const int nbN = (N + 127) / 128;   // 157

    // fold fin/out linear tail into a single [H] vector
    combine_final<<<1, H>>>(fin_w, fin_b, out_w, out_b);

    // encoders
    gemm_tf32<<<dim3(H / 128, nbE), 256>>>(edge_attr, ew, eb, p_ein, E, H, FE);
    gemm_tf32<<<dim3(H / 128, nbN), 256>>>(x, vw, vb, p_vin, N, H, FV);

    for (int k = 0; k < NL; k++) {
        gemm_tf32<<<dim3(H / 128, nbN), 256>>>(p_vin, Lv_w + (size_t)k * H * H,
                                               Lv_b + k * H, p_vp, N, H, H);
        gemm_tf32<<<dim3(H / 128, nbE), 256>>>(p_ein, Le_w + (size_t)k * H * H,
                                               Le_b + k * H, p_t, E, H, H);

        // BN-e stats (fused with +vp[src]+vp[dst])
        zero_k<<<1, 256>>>(p_sum, H);
        zero_k<<<1, 256>>>(p_sumsq, H);
        edge_pre_bn<<<2048, 256>>>(p_t, p_vp, src, dst, E);
        bn_finalize<<<1, H>>>(bne_g + k * H, bne_b + k * H, 1.0f / (float)E);

        // scatter-max + e_in residual
        zero_k<<<(N * H + 255) / 256, 256>>>(p_vie, N * H);
        bn_relu_scatter<<<4096, 256>>>(p_t, p_ein, p_vie, src, dst, E);

        // GRU
        gemm_tf32<<<dim3(3 * H / 128, nbN), 256>>>(p_vie, gru_wih + (size_t)k * 3 * H * H,
                                                   gru_bih + (size_t)k * 3 * H, p_gi,
                                                   N, 3 * H, H);
        gemm_tf32<<<dim3(3 * H / 128, nbN), 256>>>(p_vin, gru_whh + (size_t)k * 3 * H * H,
                                                   gru_bhh + (size_t)k * 3 * H, p_gh,
                                                   N, 3 * H, H);
        zero_k<<<1, 256>>>(p_sum, H);
        zero_k<<<1, 256>>>(p_sumsq, H);
        gru_elem<<<512, 256>>>(p_gi, p_gh, p_vin, p_hbuf, N);
        bn_finalize<<<1, H>>>(bnv_g + k * H, bnv_b + k * H, 1.0f / (float)N);
        v_update<<<2048, 256>>>(p_vin, p_hbuf, N * H);
    }

    // out[e] = dot(e_in[e], w_comb) + b_comb
    final_out<<<(E * 32 + 255) / 256, 256>>>(p_ein, out, E);
}

// round 3
// speedup vs baseline: 1.9385x; 1.0074x over previous
#include <cuda_runtime.h>
#include <math.h>
#include <stdint.h>

// ---------------------------------------------------------------------------
// Problem constants
// ---------------------------------------------------------------------------
constexpr int NN  = 20000;     // nodes
constexpr int NE  = 320000;    // edges
constexpr int H   = 256;       // hidden
constexpr int FE  = 64;        // edge feat
constexpr int FV  = 64;        // vertex feat
constexpr int NL  = 4;         // layers
constexpr int FL  = 1024;      // final hidden

// ---------------------------------------------------------------------------
// Scratch (device globals; no dynamic allocation allowed)
// ---------------------------------------------------------------------------
__device__ float g_ein[(size_t)NE * H];     // e_in
__device__ float g_t  [(size_t)NE * H];     // per-layer edge temp
__device__ float g_vin[(size_t)NN * H];     // v_in
__device__ float g_vp [(size_t)NN * H];     // vp
__device__ float g_vie[(size_t)NN * H];     // scatter-max result
__device__ float g_gi [(size_t)NN * 3 * H];
__device__ float g_gh [(size_t)NN * 3 * H];
__device__ float g_hbuf[(size_t)NN * H];
__device__ float g_wcomb[H];
__device__ float g_bcomb[1];
__device__ float g_sum[H];
__device__ float g_sumsq[H];
__device__ float g_scale[H];
__device__ float g_shift[H];

// ---------------------------------------------------------------------------
// Utility: zero a float buffer
// ---------------------------------------------------------------------------
__global__ void zero_k(float* __restrict__ p, int n) {
    int i = blockIdx.x * blockDim.x + threadIdx.x;
    if (i < n) p[i] = 0.0f;
}

// ---------------------------------------------------------------------------
// Fold fin/out linear layers: w_comb[h] = sum_f out_w[f]*fin_w[f,h]
// ---------------------------------------------------------------------------
__global__ void combine_final(const float* __restrict__ fin_w,   // [FL,H]
                              const float* __restrict__ fin_b,   // [FL]
                              const float* __restrict__ out_w,   // [1,FL]
                              const float* __restrict__ out_b) { // [1]
    int h = threadIdx.x;
    float s = 0.0f;
    for (int f = 0; f < FL; f++) s += out_w[f] * fin_w[(size_t)f * H + h];
    g_wcomb[h] = s;
    if (h == 0) {
        float b = out_b[0];
        for (int f = 0; f < FL; f++) b += out_w[f] * fin_b[f];
        g_bcomb[0] = b;
    }
}

// ---------------------------------------------------------------------------
// TF32 tensor-core GEMM: Y[M,Nc] = X[M,K] @ W[Nc,K]^T + bias[Nc]
// 128x128 block tile, BK=16, 256 threads = 8 warps (2x4), warp tile 64x32.
// mma.sync.m16n8k8 tf32, fp32 accum, 3-stage cp.async pipeline, one
// __syncthreads per K-step.
// FUSE variant (edge layer): epilogue adds vp[src]+vp[dst], accumulates BN
// sum/sumsq into g_sum/g_sumsq (caller must zero them first).
// Requires: K % 16 == 0, Nc % 128 == 0. M arbitrary.
// ---------------------------------------------------------------------------
#define SM_STRIDE 20
#define TILE_FLOATS (128 * SM_STRIDE)
#define NSTAGE 3
#define GEMM_SMEM_BYTES (NSTAGE * TILE_FLOATS * 4 * 2)

__device__ __forceinline__ void cp_async16(uint32_t smem, const void* gmem, int sz) {
    asm volatile("cp.async.cg.shared.global [%0], [%1], 16, %2;\n"
                 :: "r"(smem), "l"(gmem), "r"(sz));
}
__device__ __forceinline__ void cp_commit() { asm volatile("cp.async.commit_group;\n"); }
template<int NWAIT> __device__ __forceinline__ void cp_wait() {
    asm volatile("cp.async.wait_group %0;\n" :: "n"(NWAIT));
}
__device__ __forceinline__ uint32_t f2tf32(float f) {
    uint32_t u;
    asm("cvt.rna.tf32.f32 %0, %1;\n" : "=r"(u) : "f"(f));
    return u;
}

template<bool FUSE>
__global__ __launch_bounds__(256)
void gemm_tf32(const float* __restrict__ X, const float* __restrict__ W,
               const float* __restrict__ bias, float* __restrict__ Y,
               int M, int Nc, int K,
               const float* __restrict__ vp, const int* __restrict__ src,
               const int* __restrict__ dst) {
    extern __shared__ float sm[];
    float* As = sm;
    float* Bs = sm + NSTAGE * TILE_FLOATS;

    const int tid  = threadIdx.x;
    const int lane = tid & 31;
    const int warp = tid >> 5;
    const int wm   = (warp >> 2) * 64;   // warp row offset (0,64)
    const int wn   = (warp & 3) * 32;    // warp col offset (0,32,64,96)
    const int bm   = blockIdx.y * 128;
    const int bn   = blockIdx.x * 128;

    float acc[4][4][4];
#pragma unroll
    for (int i = 0; i < 4; i++)
#pragma unroll
        for (int j = 0; j < 4; j++)
#pragma unroll
            for (int c = 0; c < 4; c++) acc[i][j][c] = 0.0f;

    const int KT = K >> 4;   // BK = 16

    auto load_tile = [&](int buf, int kt) {
        float* AsB = As + buf * TILE_FLOATS;
        float* BsB = Bs + buf * TILE_FLOATS;
#pragma unroll
        for (int i = 0; i < 2; i++) {
            int id  = tid + i * 256;
            int row = id >> 2;
            int c4  = (id & 3) << 2;
            int ar  = bm + row;
            int ok  = (ar < M) ? 16 : 0;
            int arc = (ar < M) ? ar : (M - 1);
            uint32_t sa = (uint32_t)__cvta_generic_to_shared(&AsB[row * SM_STRIDE + c4]);
            cp_async16(sa, X + (size_t)arc * K + kt * 16 + c4, ok);
            int br = bn + row;   // Nc % 128 == 0 -> valid
            uint32_t sb = (uint32_t)__cvta_generic_to_shared(&BsB[row * SM_STRIDE + c4]);
            cp_async16(sb, W + (size_t)br * K + kt * 16 + c4, 16);
        }
        cp_commit();
    };

    load_tile(0, 0);
    if (KT > 1) load_tile(1, 1);

    for (int kt = 0; kt < KT; kt++) {
        if (kt + 1 < KT) cp_wait<1>(); else cp_wait<0>();
        __syncthreads();
        if (kt + 2 < KT) load_tile((kt + 2) % NSTAGE, kt + 2);

        const float* AsB = As + (kt % NSTAGE) * TILE_FLOATS;
        const float* BsB = Bs + (kt % NSTAGE) * TILE_FLOATS;

#pragma unroll
        for (int ks = 0; ks < 2; ks++) {
            const int kb = ks * 8 + (lane & 3);
            uint32_t a[4][4], b[4][2];
#pragma unroll
            for (int mf = 0; mf < 4; mf++) {
                int r0 = wm + mf * 16 + (lane >> 2);
                a[mf][0] = f2tf32(AsB[r0 * SM_STRIDE + kb]);
                a[mf][1] = f2tf32(AsB[(r0 + 8) * SM_STRIDE + kb]);
                a[mf][2] = f2tf32(AsB[r0 * SM_STRIDE + kb + 4]);
                a[mf][3] = f2tf32(AsB[(r0 + 8) * SM_STRIDE + kb + 4]);
            }
#pragma unroll
            for (int nf = 0; nf < 4; nf++) {
                int cc = wn + nf * 8 + (lane >> 2);
                b[nf][0] = f2tf32(BsB[cc * SM_STRIDE + kb]);
                b[nf][1] = f2tf32(BsB[cc * SM_STRIDE + kb + 4]);
            }
#pragma unroll
            for (int mf = 0; mf < 4; mf++)
#pragma unroll
                for (int nf = 0; nf < 4; nf++) {
                    asm volatile(
                        "mma.sync.aligned.m16n8k8.row.col.f32.tf32.tf32.f32 "
                        "{%0,%1,%2,%3},{%4,%5,%6,%7},{%8,%9},{%0,%1,%2,%3};\n"
                        : "+f"(acc[mf][nf][0]), "+f"(acc[mf][nf][1]),
                          "+f"(acc[mf][nf][2]), "+f"(acc[mf][nf][3])
                        : "r"(a[mf][0]), "r"(a[mf][1]), "r"(a[mf][2]), "r"(a[mf][3]),
                          "r"(b[nf][0]), "r"(b[nf][1]));
                }
        }
    }

    // bias values for this thread's 8 columns
    float bv[4][2];
#pragma unroll
    for (int nf = 0; nf < 4; nf++) {
        int col = bn + wn + nf * 8 + (lane & 3) * 2;
        bv[nf][0] = bias[col];
        bv[nf][1] = bias[col + 1];
    }

    if (!FUSE) {
#pragma unroll
        for (int nf = 0; nf < 4; nf++) {
            int col = bn + wn + nf * 8 + (lane & 3) * 2;
#pragma unroll
            for (int mf = 0; mf < 4; mf++) {
                int row = bm + wm + mf * 16 + (lane >> 2);
                if (row < M) {
                    float2 o = make_float2(acc[mf][nf][0] + bv[nf][0],
                                           acc[mf][nf][1] + bv[nf][1]);
                    *(float2*)(Y + (size_t)row * Nc + col) = o;
                }
                if (row + 8 < M) {
                    float2 o = make_float2(acc[mf][nf][2] + bv[nf][0],
                                           acc[mf][nf][3] + bv[nf][1]);
                    *(float2*)(Y + (size_t)(row + 8) * Nc + col) = o;
                }
            }
        }
    } else {
        // Fused epilogue: t = acc + bias + vp[src] + vp[dst]; BN stats.
        float csum[8], csq[8];
#pragma unroll
        for (int i = 0; i < 8; i++) { csum[i] = 0.f; csq[i] = 0.f; }

#pragma unroll
        for (int mf = 0; mf < 4; mf++) {
#pragma unroll
            for (int half = 0; half < 2; half++) {
                int row = bm + wm + mf * 16 + (lane >> 2) + half * 8;
                if (row < M) {
                    int va = src[row], vb = dst[row];
                    const float* pa = vp + (size_t)va * 256;
                    const float* pb = vp + (size_t)vb * 256;
#pragma unroll
                    for (int nf = 0; nf < 4; nf++) {
                        int col = bn + wn + nf * 8 + (lane & 3) * 2;
                        float2 ga = *(const float2*)(pa + col);
                        float2 gb = *(const float2*)(pb + col);
                        float v0 = acc[mf][nf][half * 2 + 0] + bv[nf][0] + ga.x + gb.x;
                        float v1 = acc[mf][nf][half * 2 + 1] + bv[nf][1] + ga.y + gb.y;
                        *(float2*)(Y + (size_t)row * Nc + col) = make_float2(v0, v1);
                        csum[nf * 2 + 0] += v0;  csq[nf * 2 + 0] += v0 * v0;
                        csum[nf * 2 + 1] += v1;  csq[nf * 2 + 1] += v1 * v1;
                    }
                }
            }
        }
        // reduce across the 8 lanes (lane>>2) sharing each column set
#pragma unroll
        for (int off = 16; off >= 4; off >>= 1) {
#pragma unroll
            for (int i = 0; i < 8; i++) {
                csum[i] += __shfl_xor_sync(0xFFFFFFFFu, csum[i], off);
                csq[i]  += __shfl_xor_sync(0xFFFFFFFFu, csq[i],  off);
            }
        }
        __syncthreads();          // done reading smem tiles; reuse for stats
        float* ssum = sm;         // [128]
        float* ssq  = sm + 128;   // [128]
        if (tid < 128) { ssum[tid] = 0.f; ssq[tid] = 0.f; }
        __syncthreads();
        if (lane < 4) {
#pragma unroll
            for (int nf = 0; nf < 4; nf++) {
#pragma unroll
                for (int c = 0; c < 2; c++) {
                    int lcol = wn + nf * 8 + lane * 2 + c;   // 0..127
                    atomicAdd(&ssum[lcol], csum[nf * 2 + c]);
                    atomicAdd(&ssq[lcol],  csq[nf * 2 + c]);
                }
            }
        }
        __syncthreads();
        if (tid < 128) {
            atomicAdd(&g_sum[bn + tid],   ssum[tid]);
            atomicAdd(&g_sumsq[bn + tid], ssq[tid]);
        }
    }
}

// ---------------------------------------------------------------------------
// Finalize BN: scale/shift per channel (biased variance, eps=1e-5)
// ---------------------------------------------------------------------------
__global__ void bn_finalize(const float* __restrict__ g, const float* __restrict__ b,
                            float inv_n) {
    int h = threadIdx.x;
    float mean = g_sum[h] * inv_n;
    float var = g_sumsq[h] * inv_n - mean * mean;
    float sc = g[h] * rsqrtf(var + 1e-5f);
    g_scale[h] = sc;
    g_shift[h] = b[h] - mean * sc;
}

// ---------------------------------------------------------------------------
// ep = relu(bn(t)); scatter-max into vie[src], vie[dst]; e_in += ep
// float4 vectorized: one (src,dst) load per 4 channels.
// ---------------------------------------------------------------------------
__global__ void bn_relu_scatter(const float4* __restrict__ t, float4* __restrict__ ein,
                                float* __restrict__ vie, const int* __restrict__ src,
                                const int* __restrict__ dst, int E) {
    size_t total = (size_t)E * (H / 4);
    size_t stride = (size_t)gridDim.x * blockDim.x;
    for (size_t idx = (size_t)blockIdx.x * blockDim.x + threadIdx.x; idx < total;
         idx += stride) {
        int c4 = (int)(idx & 63);          // H/4 = 64
        int r  = (int)(idx >> 6);
        int h4 = c4 << 2;
        float4 tv = t[idx];
        float4 v;
        v.x = fmaxf(fmaf(tv.x, g_scale[h4 + 0], g_shift[h4 + 0]), 0.f);
        v.y = fmaxf(fmaf(tv.y, g_scale[h4 + 1], g_shift[h4 + 1]), 0.f);
        v.z = fmaxf(fmaf(tv.z, g_scale[h4 + 2], g_shift[h4 + 2]), 0.f);
        v.w = fmaxf(fmaf(tv.w, g_scale[h4 + 3], g_shift[h4 + 3]), 0.f);
        int a = src[r], b = dst[r];
        int* pa = (int*)&vie[(size_t)a * H + h4];
        int* pb = (int*)&vie[(size_t)b * H + h4];
        atomicMax(pa + 0, __float_as_int(v.x));
        atomicMax(pa + 1, __float_as_int(v.y));
        atomicMax(pa + 2, __float_as_int(v.z));
        atomicMax(pa + 3, __float_as_int(v.w));
        atomicMax(pb + 0, __float_as_int(v.x));
        atomicMax(pb + 1, __float_as_int(v.y));
        atomicMax(pb + 2, __float_as_int(v.z));
        atomicMax(pb + 3, __float_as_int(v.w));
        float4 e = ein[idx];
        e.x += v.x; e.y += v.y; e.z += v.z; e.w += v.w;
        ein[idx] = e;
    }
}

// ---------------------------------------------------------------------------
// GRU gate math + BN stats on h.
// ---------------------------------------------------------------------------
__global__ void gru_elem(const float* __restrict__ gi, const float* __restrict__ gh,
                         const float* __restrict__ vin, float* __restrict__ hbuf,
                         int N) {
    size_t total = (size_t)N * H;
    size_t stride = (size_t)gridDim.x * blockDim.x;   // multiple of 256
    int h = threadIdx.x & (H - 1);
    float s = 0.f, s2 = 0.f;
    bool any = false;
    for (size_t idx = (size_t)blockIdx.x * blockDim.x + threadIdx.x; idx < total;
         idx += stride) {
        int n = (int)(idx >> 8);
        const float* giR = gi + (size_t)n * (3 * H);
        const float* ghR = gh + (size_t)n * (3 * H);
        float ir = giR[h], iz = giR[h + H], ig = giR[h + 2 * H];
        float hr = ghR[h], hz = ghR[h + H], hg = ghR[h + 2 * H];
        float r = 1.0f / (1.0f + expf(-(ir + hr)));
        float z = 1.0f / (1.0f + expf(-(iz + hz)));
        float nn = tanhf(ig + r * hg);
        float hv = (1.0f - z) * nn + z * vin[idx];
        hbuf[idx] = hv;
        s += hv;
        s2 += hv * hv;
        any = true;
    }
    if (any) {
        atomicAdd(&g_sum[h], s);
        atomicAdd(&g_sumsq[h], s2);
    }
}

// ---------------------------------------------------------------------------
// v_in += relu(bn(hbuf))
// ---------------------------------------------------------------------------
__global__ void v_update(float* __restrict__ vin, const float* __restrict__ hbuf,
                         int total) {
    int stride = gridDim.x * blockDim.x;
    for (int idx = blockIdx.x * blockDim.x + threadIdx.x; idx < total; idx += stride) {
        int h = idx & (H - 1);
        float v = fmaf(hbuf[idx], g_scale[h], g_shift[h]);
        vin[idx] += fmaxf(v, 0.0f);
    }
}

// ---------------------------------------------------------------------------
// out[e] = dot(e_in[e], w_comb) + b_comb   (one warp per edge)
// ---------------------------------------------------------------------------
__global__ void final_out(const float* __restrict__ ein, float* __restrict__ out,
                          int E) {
    int warp = (blockIdx.x * blockDim.x + threadIdx.x) >> 5;
    int lane = threadIdx.x & 31;
    if (warp >= E) return;
    const float* row = ein + (size_t)warp * H;
    float s = 0.f;
#pragma unroll
    for (int j = 0; j < 8; j++) {
        int c = j * 32 + lane;
        s = fmaf(row[c], g_wcomb[c], s);
    }
#pragma unroll
    for (int o = 16; o > 0; o >>= 1) s += __shfl_xor_sync(0xFFFFFFFFu, s, o);
    if (lane == 0) out[warp] = s + g_bcomb[0];
}

// ---------------------------------------------------------------------------
// Launch
// ---------------------------------------------------------------------------
extern "C" void kernel_launch(void* const* d_in, const int* in_sizes, int n_in,
                              void* d_out, int out_size) {
    const float* x         = (const float*)d_in[0];
    const float* edge_attr = (const float*)d_in[1];
    const int*   edge_idx  = (const int*)  d_in[2];
    const float* ew        = (const float*)d_in[3];
    const float* eb        = (const float*)d_in[4];
    const float* vw        = (const float*)d_in[5];
    const float* vb        = (const float*)d_in[6];
    const float* Le_w      = (const float*)d_in[7];
    const float* Le_b      = (const float*)d_in[8];
    const float* Lv_w      = (const float*)d_in[9];
    const float* Lv_b      = (const float*)d_in[10];
    const float* bne_g     = (const float*)d_in[11];
    const float* bne_b     = (const float*)d_in[12];
    const float* bnv_g     = (const float*)d_in[13];
    const float* bnv_b     = (const float*)d_in[14];
    const float* gru_wih   = (const float*)d_in[15];
    const float* gru_whh   = (const float*)d_in[16];
    const float* gru_bih   = (const float*)d_in[17];
    const float* gru_bhh   = (const float*)d_in[18];
    const float* fin_w     = (const float*)d_in[19];
    const float* fin_b     = (const float*)d_in[20];
    const float* out_w     = (const float*)d_in[21];
    const float* out_b     = (const float*)d_in[22];
    float* out = (float*)d_out;

    const int E = in_sizes[1] / FE;
    const int N = in_sizes[0] / FV;
    const int* src = edge_idx;
    const int* dst = edge_idx + E;

    float *p_ein, *p_t, *p_vin, *p_vp, *p_vie, *p_gi, *p_gh, *p_hbuf, *p_sum, *p_sumsq;
    cudaGetSymbolAddress((void**)&p_ein,  g_ein);
    cudaGetSymbolAddress((void**)&p_t,    g_t);
    cudaGetSymbolAddress((void**)&p_vin,  g_vin);
    cudaGetSymbolAddress((void**)&p_vp,   g_vp);
    cudaGetSymbolAddress((void**)&p_vie,  g_vie);
    cudaGetSymbolAddress((void**)&p_gi,   g_gi);
    cudaGetSymbolAddress((void**)&p_gh,   g_gh);
    cudaGetSymbolAddress((void**)&p_hbuf, g_hbuf);
    cudaGetSymbolAddress((void**)&p_sum,  g_sum);
    cudaGetSymbolAddress((void**)&p_sumsq,g_sumsq);

    cudaFuncSetAttribute(gemm_tf32<false>, cudaFuncAttributeMaxDynamicSharedMemorySize,
                         GEMM_SMEM_BYTES);
    cudaFuncSetAttribute(gemm_tf32<true>,  cudaFuncAttributeMaxDynamicSharedMemorySize,
                         GEMM_SMEM_BYTES);

    const int nbE = (E + 127) / 128;   // 2500
    const int nbN = (N + 127) / 128;   // 157

    // fold fin/out linear tail into a single [H] vector
    combine_final<<<1, H>>>(fin_w, fin_b, out_w, out_b);

    // encoders
    gemm_tf32<false><<<dim3(H / 128, nbE), 256, GEMM_SMEM_BYTES>>>(
        edge_attr, ew, eb, p_ein, E, H, FE, nullptr, nullptr, nullptr);
    gemm_tf32<false><<<dim3(H / 128, nbN), 256, GEMM_SMEM_BYTES>>>(
        x, vw, vb, p_vin, N, H, FV, nullptr, nullptr, nullptr);

    for (int k = 0; k < NL; k++) {
        // vp = v_in @ Lv_w^T + Lv_b
        gemm_tf32<false><<<dim3(H / 128, nbN), 256, GEMM_SMEM_BYTES>>>(
            p_vin, Lv_w + (size_t)k * H * H, Lv_b + k * H, p_vp, N, H, H,
            nullptr, nullptr, nullptr);

        // t = e_in @ Le_w^T + Le_b + vp[src] + vp[dst]  (+ BN stats, fused)
        zero_k<<<1, 256>>>(p_sum, H);
        zero_k<<<1, 256>>>(p_sumsq, H);
        gemm_tf32<true><<<dim3(H / 128, nbE), 256, GEMM_SMEM_BYTES>>>(
            p_ein, Le_w + (size_t)k * H * H, Le_b + k * H, p_t, E, H, H,
            p_vp, src, dst);
        bn_finalize<<<1, H>>>(bne_g + k * H, bne_b + k * H, 1.0f / (float)E);

        // scatter-max + e_in residual
        zero_k<<<(N * H + 255) / 256, 256>>>(p_vie, N * H);
        bn_relu_scatter<<<4096, 256>>>((const float4*)p_t, (float4*)p_ein, p_vie,
                                       src, dst, E);

        // GRU
        gemm_tf32<false><<<dim3(3 * H / 128, nbN), 256, GEMM_SMEM_BYTES>>>(
            p_vie, gru_wih + (size_t)k * 3 * H * H, gru_bih + (size_t)k * 3 * H,
            p_gi, N, 3 * H, H, nullptr, nullptr, nullptr);
        gemm_tf32<false><<<dim3(3 * H / 128, nbN), 256, GEMM_SMEM_BYTES>>>(
            p_vin, gru_whh + (size_t)k * 3 * H * H, gru_bhh + (size_t)k * 3 * H,
            p_gh, N, 3 * H, H, nullptr, nullptr, nullptr);
        zero_k<<<1, 256>>>(p_sum, H);
        zero_k<<<1, 256>>>(p_sumsq, H);
        gru_elem<<<512, 256>>>(p_gi, p_gh, p_vin, p_hbuf, N);
        bn_finalize<<<1, H>>>(bnv_g + k * H, bnv_b + k * H, 1.0f / (float)N);
        v_update<<<2048, 256>>>(p_vin, p_hbuf, N * H);
    }

    // out[e] = dot(e_in[e], w_comb) + b_comb
    final_out<<<(E * 32 + 255) / 256, 256>>>(p_ein, out, E);
}

// round 4
// speedup vs baseline: 1.9544x; 1.0082x over previous
#include <cuda_runtime.h>
#include <math.h>
#include <stdint.h>

// ---------------------------------------------------------------------------
// Problem constants
// ---------------------------------------------------------------------------
constexpr int NN  = 20000;     // nodes
constexpr int NE  = 320000;    // edges
constexpr int H   = 256;       // hidden
constexpr int FE  = 64;        // edge feat
constexpr int FV  = 64;        // vertex feat
constexpr int NL  = 4;         // layers
constexpr int FL  = 1024;      // final hidden

// ---------------------------------------------------------------------------
// Scratch (device globals; no dynamic allocation allowed)
// ---------------------------------------------------------------------------
__device__ float g_ein[(size_t)NE * H];     // e_in
__device__ float g_t  [(size_t)NE * H];     // per-layer edge temp
__device__ float g_vin[(size_t)NN * H];     // v_in
__device__ float g_vp [(size_t)NN * H];     // vp
__device__ float g_vie[(size_t)NN * H];     // scatter-max result
__device__ float g_gi [(size_t)NN * 3 * H];
__device__ float g_gh [(size_t)NN * 3 * H];
__device__ float g_hbuf[(size_t)NN * H];
__device__ float g_wcomb[H];
__device__ float g_bcomb[1];
__device__ float g_sum[H];
__device__ float g_sumsq[H];
__device__ float g_scale[H];
__device__ float g_shift[H];

// ---------------------------------------------------------------------------
// Utility: zero a float buffer
// ---------------------------------------------------------------------------
__global__ void zero_k(float* __restrict__ p, int n) {
    int i = blockIdx.x * blockDim.x + threadIdx.x;
    if (i < n) p[i] = 0.0f;
}

// ---------------------------------------------------------------------------
// Fold fin/out linear layers: w_comb[h] = sum_f out_w[f]*fin_w[f,h]
// ---------------------------------------------------------------------------
__global__ void combine_final(const float* __restrict__ fin_w,   // [FL,H]
                              const float* __restrict__ fin_b,   // [FL]
                              const float* __restrict__ out_w,   // [1,FL]
                              const float* __restrict__ out_b) { // [1]
    int h = threadIdx.x;
    float s = 0.0f;
    for (int f = 0; f < FL; f++) s += out_w[f] * fin_w[(size_t)f * H + h];
    g_wcomb[h] = s;
    if (h == 0) {
        float b = out_b[0];
        for (int f = 0; f < FL; f++) b += out_w[f] * fin_b[f];
        g_bcomb[0] = b;
    }
}

// ---------------------------------------------------------------------------
// TF32 tensor-core GEMM: Y[M,Nc] = X[M,K] @ W[Nc,K]^T + bias[Nc]
// 128x128 block tile, BK=16, 256 threads = 8 warps (2x4), warp tile 64x32.
// Loader: LDG.128 -> cvt.rna.tf32 (once per element) -> STS.128, register
// double-buffered across two smem stages, ONE __syncthreads per K-step.
// Inner loop: ldmatrix.x4.b16 fragment loads (tf32 maps exactly onto 8x8
// b16 tiles) + mma.sync.m16n8k8 -> pure LDSM + HMMA.
// FUSE variant (edge layer): epilogue adds vp[src]+vp[dst], accumulates BN
// sum/sumsq into g_sum/g_sumsq (caller must zero them first).
// Requires: K % 16 == 0, Nc % 128 == 0. M arbitrary.
// ---------------------------------------------------------------------------
#define SM_STRIDE 20
#define TILE_FLOATS (128 * SM_STRIDE)
#define TILE_BYTES  (TILE_FLOATS * 4)

__device__ __forceinline__ uint32_t f2tf32(float f) {
    uint32_t u;
    asm("cvt.rna.tf32.f32 %0, %1;\n" : "=r"(u) : "f"(f));
    return u;
}
__device__ __forceinline__ void ldsm_x4(uint32_t& r0, uint32_t& r1,
                                        uint32_t& r2, uint32_t& r3, uint32_t addr) {
    asm volatile("ldmatrix.sync.aligned.m8n8.x4.shared.b16 {%0,%1,%2,%3}, [%4];\n"
                 : "=r"(r0), "=r"(r1), "=r"(r2), "=r"(r3) : "r"(addr));
}

template<bool FUSE>
__global__ __launch_bounds__(256)
void gemm_tf32(const float* __restrict__ X, const float* __restrict__ W,
               const float* __restrict__ bias, float* __restrict__ Y,
               int M, int Nc, int K,
               const float* __restrict__ vp, const int* __restrict__ src,
               const int* __restrict__ dst) {
    __shared__ float As[2][TILE_FLOATS];
    __shared__ float Bs[2][TILE_FLOATS];

    const int tid  = threadIdx.x;
    const int lane = tid & 31;
    const int warp = tid >> 5;
    const int wm   = (warp >> 2) * 64;   // warp row offset (0,64)
    const int wn   = (warp & 3) * 32;    // warp col offset (0,32,64,96)
    const int bm   = blockIdx.y * 128;
    const int bn   = blockIdx.x * 128;

    float acc[4][4][4];
#pragma unroll
    for (int i = 0; i < 4; i++)
#pragma unroll
        for (int j = 0; j < 4; j++)
#pragma unroll
            for (int c = 0; c < 4; c++) acc[i][j][c] = 0.0f;

    const int KT = K >> 4;   // BK = 16

    // loader mapping: 512 float4 per tile per matrix; 2 per thread
    const int l_row0 = tid >> 2;              // 0..63
    const int l_row1 = (tid + 256) >> 2;      // 64..127
    const int l_c4   = (tid & 3) << 2;        // 0,4,8,12

    // ldmatrix per-lane byte offsets
    const uint32_t smA = (uint32_t)__cvta_generic_to_shared(&As[0][0]);
    const uint32_t smB = (uint32_t)__cvta_generic_to_shared(&Bs[0][0]);
    const uint32_t a_lane = ((wm + (lane & 15)) * SM_STRIDE + (lane >> 4) * 4) * 4;
    const uint32_t b_lane = ((wn + (lane >> 4) * 8 + (lane & 7)) * SM_STRIDE
                             + ((lane >> 3) & 1) * 4) * 4;

    float4 ra0, ra1, rb0, rb1;
    auto ldg_tile = [&](int kt) {
        const float4 z = make_float4(0.f, 0.f, 0.f, 0.f);
        int ar0 = bm + l_row0, ar1 = bm + l_row1;
        ra0 = (ar0 < M) ? *(const float4*)(X + (size_t)ar0 * K + kt * 16 + l_c4) : z;
        ra1 = (ar1 < M) ? *(const float4*)(X + (size_t)ar1 * K + kt * 16 + l_c4) : z;
        rb0 = *(const float4*)(W + (size_t)(bn + l_row0) * K + kt * 16 + l_c4);
        rb1 = *(const float4*)(W + (size_t)(bn + l_row1) * K + kt * 16 + l_c4);
    };
    auto sts_tile = [&](int buf) {
        uint4 ta0 = make_uint4(f2tf32(ra0.x), f2tf32(ra0.y), f2tf32(ra0.z), f2tf32(ra0.w));
        uint4 ta1 = make_uint4(f2tf32(ra1.x), f2tf32(ra1.y), f2tf32(ra1.z), f2tf32(ra1.w));
        uint4 tb0 = make_uint4(f2tf32(rb0.x), f2tf32(rb0.y), f2tf32(rb0.z), f2tf32(rb0.w));
        uint4 tb1 = make_uint4(f2tf32(rb1.x), f2tf32(rb1.y), f2tf32(rb1.z), f2tf32(rb1.w));
        *(uint4*)&As[buf][l_row0 * SM_STRIDE + l_c4] = ta0;
        *(uint4*)&As[buf][l_row1 * SM_STRIDE + l_c4] = ta1;
        *(uint4*)&Bs[buf][l_row0 * SM_STRIDE + l_c4] = tb0;
        *(uint4*)&Bs[buf][l_row1 * SM_STRIDE + l_c4] = tb1;
    };

    ldg_tile(0);
    sts_tile(0);

    for (int kt = 0; kt < KT; kt++) {
        __syncthreads();
        const int buf = kt & 1;
        if (kt + 1 < KT) ldg_tile(kt + 1);

        const uint32_t baseA = smA + buf * TILE_BYTES + a_lane;
        const uint32_t baseB = smB + buf * TILE_BYTES + b_lane;

#pragma unroll
        for (int ks = 0; ks < 2; ks++) {
            uint32_t a[4][4], bq[2][4];
#pragma unroll
            for (int mf = 0; mf < 4; mf++)
                ldsm_x4(a[mf][0], a[mf][1], a[mf][2], a[mf][3],
                        baseA + (mf * 16 * SM_STRIDE + ks * 8) * 4);
#pragma unroll
            for (int j = 0; j < 2; j++)
                ldsm_x4(bq[j][0], bq[j][1], bq[j][2], bq[j][3],
                        baseB + (j * 16 * SM_STRIDE + ks * 8) * 4);
#pragma unroll
            for (int mf = 0; mf < 4; mf++)
#pragma unroll
                for (int nf = 0; nf < 4; nf++) {
                    uint32_t b0 = bq[nf >> 1][(nf & 1) * 2 + 0];
                    uint32_t b1 = bq[nf >> 1][(nf & 1) * 2 + 1];
                    asm volatile(
                        "mma.sync.aligned.m16n8k8.row.col.f32.tf32.tf32.f32 "
                        "{%0,%1,%2,%3},{%4,%5,%6,%7},{%8,%9},{%0,%1,%2,%3};\n"
                        : "+f"(acc[mf][nf][0]), "+f"(acc[mf][nf][1]),
                          "+f"(acc[mf][nf][2]), "+f"(acc[mf][nf][3])
                        : "r"(a[mf][0]), "r"(a[mf][1]), "r"(a[mf][2]), "r"(a[mf][3]),
                          "r"(b0), "r"(b1));
                }
        }
        if (kt + 1 < KT) sts_tile(buf ^ 1);
    }

    // bias values for this thread's 8 columns
    float bv[4][2];
#pragma unroll
    for (int nf = 0; nf < 4; nf++) {
        int col = bn + wn + nf * 8 + (lane & 3) * 2;
        bv[nf][0] = bias[col];
        bv[nf][1] = bias[col + 1];
    }

    if (!FUSE) {
#pragma unroll
        for (int nf = 0; nf < 4; nf++) {
            int col = bn + wn + nf * 8 + (lane & 3) * 2;
#pragma unroll
            for (int mf = 0; mf < 4; mf++) {
                int row = bm + wm + mf * 16 + (lane >> 2);
                if (row < M) {
                    float2 o = make_float2(acc[mf][nf][0] + bv[nf][0],
                                           acc[mf][nf][1] + bv[nf][1]);
                    *(float2*)(Y + (size_t)row * Nc + col) = o;
                }
                if (row + 8 < M) {
                    float2 o = make_float2(acc[mf][nf][2] + bv[nf][0],
                                           acc[mf][nf][3] + bv[nf][1]);
                    *(float2*)(Y + (size_t)(row + 8) * Nc + col) = o;
                }
            }
        }
    } else {
        // Fused epilogue: t = acc + bias + vp[src] + vp[dst]; BN stats.
        float csum[8], csq[8];
#pragma unroll
        for (int i = 0; i < 8; i++) { csum[i] = 0.f; csq[i] = 0.f; }

#pragma unroll
        for (int mf = 0; mf < 4; mf++) {
#pragma unroll
            for (int half = 0; half < 2; half++) {
                int row = bm + wm + mf * 16 + (lane >> 2) + half * 8;
                if (row < M) {
                    int va = src[row], vb = dst[row];
                    const float* pa = vp + (size_t)va * 256;
                    const float* pb = vp + (size_t)vb * 256;
#pragma unroll
                    for (int nf = 0; nf < 4; nf++) {
                        int col = bn + wn + nf * 8 + (lane & 3) * 2;
                        float2 ga = *(const float2*)(pa + col);
                        float2 gb = *(const float2*)(pb + col);
                        float v0 = acc[mf][nf][half * 2 + 0] + bv[nf][0] + ga.x + gb.x;
                        float v1 = acc[mf][nf][half * 2 + 1] + bv[nf][1] + ga.y + gb.y;
                        *(float2*)(Y + (size_t)row * Nc + col) = make_float2(v0, v1);
                        csum[nf * 2 + 0] += v0;  csq[nf * 2 + 0] += v0 * v0;
                        csum[nf * 2 + 1] += v1;  csq[nf * 2 + 1] += v1 * v1;
                    }
                }
            }
        }
        // reduce across the 8 lanes (lane>>2) sharing each column set
#pragma unroll
        for (int off = 16; off >= 4; off >>= 1) {
#pragma unroll
            for (int i = 0; i < 8; i++) {
                csum[i] += __shfl_xor_sync(0xFFFFFFFFu, csum[i], off);
                csq[i]  += __shfl_xor_sync(0xFFFFFFFFu, csq[i],  off);
            }
        }
        __syncthreads();               // done reading smem tiles; reuse for stats
        float* ssum = &As[0][0];       // [128]
        float* ssq  = &As[0][128];     // [128]
        if (tid < 128) { ssum[tid] = 0.f; ssq[tid] = 0.f; }
        __syncthreads();
        if (lane < 4) {
#pragma unroll
            for (int nf = 0; nf < 4; nf++) {
#pragma unroll
                for (int c = 0; c < 2; c++) {
                    int lcol = wn + nf * 8 + lane * 2 + c;   // 0..127
                    atomicAdd(&ssum[lcol], csum[nf * 2 + c]);
                    atomicAdd(&ssq[lcol],  csq[nf * 2 + c]);
                }
            }
        }
        __syncthreads();
        if (tid < 128) {
            atomicAdd(&g_sum[bn + tid],   ssum[tid]);
            atomicAdd(&g_sumsq[bn + tid], ssq[tid]);
        }
    }
}

// ---------------------------------------------------------------------------
// Finalize BN: scale/shift per channel (biased variance, eps=1e-5)
// ---------------------------------------------------------------------------
__global__ void bn_finalize(const float* __restrict__ g, const float* __restrict__ b,
                            float inv_n) {
    int h = threadIdx.x;
    float mean = g_sum[h] * inv_n;
    float var = g_sumsq[h] * inv_n - mean * mean;
    float sc = g[h] * rsqrtf(var + 1e-5f);
    g_scale[h] = sc;
    g_shift[h] = b[h] - mean * sc;
}

// ---------------------------------------------------------------------------
// ep = relu(bn(t)); scatter-max into vie[src], vie[dst]; e_in += ep
// float4 vectorized: one (src,dst) load per 4 channels.
// ---------------------------------------------------------------------------
__global__ void bn_relu_scatter(const float4* __restrict__ t, float4* __restrict__ ein,
                                float* __restrict__ vie, const int* __restrict__ src,
                                const int* __restrict__ dst, int E) {
    size_t total = (size_t)E * (H / 4);
    size_t stride = (size_t)gridDim.x * blockDim.x;
    for (size_t idx = (size_t)blockIdx.x * blockDim.x + threadIdx.x; idx < total;
         idx += stride) {
        int c4 = (int)(idx & 63);          // H/4 = 64
        int r  = (int)(idx >> 6);
        int h4 = c4 << 2;
        float4 tv = t[idx];
        float4 v;
        v.x = fmaxf(fmaf(tv.x, g_scale[h4 + 0], g_shift[h4 + 0]), 0.f);
        v.y = fmaxf(fmaf(tv.y, g_scale[h4 + 1], g_shift[h4 + 1]), 0.f);
        v.z = fmaxf(fmaf(tv.z, g_scale[h4 + 2], g_shift[h4 + 2]), 0.f);
        v.w = fmaxf(fmaf(tv.w, g_scale[h4 + 3], g_shift[h4 + 3]), 0.f);
        int a = src[r], b = dst[r];
        int* pa = (int*)&vie[(size_t)a * H + h4];
        int* pb = (int*)&vie[(size_t)b * H + h4];
        atomicMax(pa + 0, __float_as_int(v.x));
        atomicMax(pa + 1, __float_as_int(v.y));
        atomicMax(pa + 2, __float_as_int(v.z));
        atomicMax(pa + 3, __float_as_int(v.w));
        atomicMax(pb + 0, __float_as_int(v.x));
        atomicMax(pb + 1, __float_as_int(v.y));
        atomicMax(pb + 2, __float_as_int(v.z));
        atomicMax(pb + 3, __float_as_int(v.w));
        float4 e = ein[idx];
        e.x += v.x; e.y += v.y; e.z += v.z; e.w += v.w;
        ein[idx] = e;
    }
}

// ---------------------------------------------------------------------------
// GRU gate math + BN stats on h.
// ---------------------------------------------------------------------------
__global__ void gru_elem(const float* __restrict__ gi, const float* __restrict__ gh,
                         const float* __restrict__ vin, float* __restrict__ hbuf,
                         int N) {
    size_t total = (size_t)N * H;
    size_t stride = (size_t)gridDim.x * blockDim.x;   // multiple of 256
    int h = threadIdx.x & (H - 1);
    float s = 0.f, s2 = 0.f;
    bool any = false;
    for (size_t idx = (size_t)blockIdx.x * blockDim.x + threadIdx.x; idx < total;
         idx += stride) {
        int n = (int)(idx >> 8);
        const float* giR = gi + (size_t)n * (3 * H);
        const float* ghR = gh + (size_t)n * (3 * H);
        float ir = giR[h], iz = giR[h + H], ig = giR[h + 2 * H];
        float hr = ghR[h], hz = ghR[h + H], hg = ghR[h + 2 * H];
        float r = 1.0f / (1.0f + expf(-(ir + hr)));
        float z = 1.0f / (1.0f + expf(-(iz + hz)));
        float nn = tanhf(ig + r * hg);
        float hv = (1.0f - z) * nn + z * vin[idx];
        hbuf[idx] = hv;
        s += hv;
        s2 += hv * hv;
        any = true;
    }
    if (any) {
        atomicAdd(&g_sum[h], s);
        atomicAdd(&g_sumsq[h], s2);
    }
}

// ---------------------------------------------------------------------------
// v_in += relu(bn(hbuf))
// ---------------------------------------------------------------------------
__global__ void v_update(float* __restrict__ vin, const float* __restrict__ hbuf,
                         int total) {
    int stride = gridDim.x * blockDim.x;
    for (int idx = blockIdx.x * blockDim.x + threadIdx.x; idx < total; idx += stride) {
        int h = idx & (H - 1);
        float v = fmaf(hbuf[idx], g_scale[h], g_shift[h]);
        vin[idx] += fmaxf(v, 0.0f);
    }
}

// ---------------------------------------------------------------------------
// out[e] = dot(e_in[e], w_comb) + b_comb   (one warp per edge)
// ---------------------------------------------------------------------------
__global__ void final_out(const float* __restrict__ ein, float* __restrict__ out,
                          int E) {
    int warp = (blockIdx.x * blockDim.x + threadIdx.x) >> 5;
    int lane = threadIdx.x & 31;
    if (warp >= E) return;
    const float* row = ein + (size_t)warp * H;
    float s = 0.f;
#pragma unroll
    for (int j = 0; j < 8; j++) {
        int c = j * 32 + lane;
        s = fmaf(row[c], g_wcomb[c], s);
    }
#pragma unroll
    for (int o = 16; o > 0; o >>= 1) s += __shfl_xor_sync(0xFFFFFFFFu, s, o);
    if (lane == 0) out[warp] = s + g_bcomb[0];
}

// ---------------------------------------------------------------------------
// Launch
// ---------------------------------------------------------------------------
extern "C" void kernel_launch(void* const* d_in, const int* in_sizes, int n_in,
                              void* d_out, int out_size) {
    const float* x         = (const float*)d_in[0];
    const float* edge_attr = (const float*)d_in[1];
    const int*   edge_idx  = (const int*)  d_in[2];
    const float* ew        = (const float*)d_in[3];
    const float* eb        = (const float*)d_in[4];
    const float* vw        = (const float*)d_in[5];
    const float* vb        = (const float*)d_in[6];
    const float* Le_w      = (const float*)d_in[7];
    const float* Le_b      = (const float*)d_in[8];
    const float* Lv_w      = (const float*)d_in[9];
    const float* Lv_b      = (const float*)d_in[10];
    const float* bne_g     = (const float*)d_in[11];
    const float* bne_b     = (const float*)d_in[12];
    const float* bnv_g     = (const float*)d_in[13];
    const float* bnv_b     = (const float*)d_in[14];
    const float* gru_wih   = (const float*)d_in[15];
    const float* gru_whh   = (const float*)d_in[16];
    const float* gru_bih   = (const float*)d_in[17];
    const float* gru_bhh   = (const float*)d_in[18];
    const float* fin_w     = (const float*)d_in[19];
    const float* fin_b     = (const float*)d_in[20];
    const float* out_w     = (const float*)d_in[21];
    const float* out_b     = (const float*)d_in[22];
    float* out = (float*)d_out;

    const int E = in_sizes[1] / FE;
    const int N = in_sizes[0] / FV;
    const int* src = edge_idx;
    const int* dst = edge_idx + E;

    float *p_ein, *p_t, *p_vin, *p_vp, *p_vie, *p_gi, *p_gh, *p_hbuf, *p_sum, *p_sumsq;
    cudaGetSymbolAddress((void**)&p_ein,  g_ein);
    cudaGetSymbolAddress((void**)&p_t,    g_t);
    cudaGetSymbolAddress((void**)&p_vin,  g_vin);
    cudaGetSymbolAddress((void**)&p_vp,   g_vp);
    cudaGetSymbolAddress((void**)&p_vie,  g_vie);
    cudaGetSymbolAddress((void**)&p_gi,   g_gi);
    cudaGetSymbolAddress((void**)&p_gh,   g_gh);
    cudaGetSymbolAddress((void**)&p_hbuf, g_hbuf);
    cudaGetSymbolAddress((void**)&p_sum,  g_sum);
    cudaGetSymbolAddress((void**)&p_sumsq,g_sumsq);

    const int nbE = (E + 127) / 128;   // 2500
    const int nbN = (N + 127) / 128;   // 157

    // fold fin/out linear tail into a single [H] vector
    combine_final<<<1, H>>>(fin_w, fin_b, out_w, out_b);

    // encoders
    gemm_tf32<false><<<dim3(H / 128, nbE), 256>>>(
        edge_attr, ew, eb, p_ein, E, H, FE, nullptr, nullptr, nullptr);
    gemm_tf32<false><<<dim3(H / 128, nbN), 256>>>(
        x, vw, vb, p_vin, N, H, FV, nullptr, nullptr, nullptr);

    for (int k = 0; k < NL; k++) {
        // vp = v_in @ Lv_w^T + Lv_b
        gemm_tf32<false><<<dim3(H / 128, nbN), 256>>>(
            p_vin, Lv_w + (size_t)k * H * H, Lv_b + k * H, p_vp, N, H, H,
            nullptr, nullptr, nullptr);

        // t = e_in @ Le_w^T + Le_b + vp[src] + vp[dst]  (+ BN stats, fused)
        zero_k<<<1, 256>>>(p_sum, H);
        zero_k<<<1, 256>>>(p_sumsq, H);
        gemm_tf32<true><<<dim3(H / 128, nbE), 256>>>(
            p_ein, Le_w + (size_t)k * H * H, Le_b + k * H, p_t, E, H, H,
            p_vp, src, dst);
        bn_finalize<<<1, H>>>(bne_g + k * H, bne_b + k * H, 1.0f / (float)E);

        // scatter-max + e_in residual
        zero_k<<<(N * H + 255) / 256, 256>>>(p_vie, N * H);
        bn_relu_scatter<<<4096, 256>>>((const float4*)p_t, (float4*)p_ein, p_vie,
                                       src, dst, E);

        // GRU
        gemm_tf32<false><<<dim3(3 * H / 128, nbN), 256>>>(
            p_vie, gru_wih + (size_t)k * 3 * H * H, gru_bih + (size_t)k * 3 * H,
            p_gi, N, 3 * H, H, nullptr, nullptr, nullptr);
        gemm_tf32<false><<<dim3(3 * H / 128, nbN), 256>>>(
            p_vin, gru_whh + (size_t)k * 3 * H * H, gru_bhh + (size_t)k * 3 * H,
            p_gh, N, 3 * H, H, nullptr, nullptr, nullptr);
        zero_k<<<1, 256>>>(p_sum, H);
        zero_k<<<1, 256>>>(p_sumsq, H);
        gru_elem<<<512, 256>>>(p_gi, p_gh, p_vin, p_hbuf, N);
        bn_finalize<<<1, H>>>(bnv_g + k * H, bnv_b + k * H, 1.0f / (float)N);
        v_update<<<2048, 256>>>(p_vin, p_hbuf, N * H);
    }

    // out[e] = dot(e_in[e], w_comb) + b_comb
    final_out<<<(E * 32 + 255) / 256, 256>>>(p_ein, out, E);
}

// round 6
// speedup vs baseline: 1.9945x; 1.0205x over previous
#include <cuda_runtime.h>
#include <math.h>
#include <stdint.h>

// ---------------------------------------------------------------------------
// Problem constants
// ---------------------------------------------------------------------------
constexpr int NN  = 20000;     // nodes
constexpr int NE  = 320000;    // edges
constexpr int H   = 256;       // hidden
constexpr int FE  = 64;        // edge feat
constexpr int FV  = 64;        // vertex feat
constexpr int NL  = 4;         // layers
constexpr int FL  = 1024;      // final hidden

// ---------------------------------------------------------------------------
// Scratch (device globals; no dynamic allocation allowed)
// ---------------------------------------------------------------------------
__device__ float g_ein[(size_t)NE * H];     // e_in
__device__ float g_t  [(size_t)NE * H];     // per-layer edge temp
__device__ float g_vin[(size_t)NN * H];     // v_in
__device__ float g_vp [(size_t)NN * H];     // vp
__device__ float g_vie[(size_t)NN * H];     // scatter-max result
__device__ float g_gi [(size_t)NN * 3 * H];
__device__ float g_gh [(size_t)NN * 3 * H];
__device__ float g_hbuf[(size_t)NN * H];
__device__ float g_wcomb[H];
__device__ float g_bcomb[1];
__device__ float g_sum[H];
__device__ float g_sumsq[H];
__device__ float g_scale[H];
__device__ float g_shift[H];

// ---------------------------------------------------------------------------
// Utility: zero a float buffer
// ---------------------------------------------------------------------------
__global__ void zero_k(float* __restrict__ p, int n) {
    int i = blockIdx.x * blockDim.x + threadIdx.x;
    if (i < n) p[i] = 0.0f;
}

// ---------------------------------------------------------------------------
// Fold fin/out linear layers: w_comb[h] = sum_f out_w[f]*fin_w[f,h]
// Also zeroes the BN stat accumulators for the first fused edge-stats pass.
// ---------------------------------------------------------------------------
__global__ void combine_final(const float* __restrict__ fin_w,   // [FL,H]
                              const float* __restrict__ fin_b,   // [FL]
                              const float* __restrict__ out_w,   // [1,FL]
                              const float* __restrict__ out_b) { // [1]
    int h = threadIdx.x;
    float s = 0.0f;
    for (int f = 0; f < FL; f++) s += out_w[f] * fin_w[(size_t)f * H + h];
    g_wcomb[h] = s;
    g_sum[h] = 0.0f;
    g_sumsq[h] = 0.0f;
    if (h == 0) {
        float b = out_b[0];
        for (int f = 0; f < FL; f++) b += out_w[f] * fin_b[f];
        g_bcomb[0] = b;
    }
}

// ---------------------------------------------------------------------------
// TF32 tensor-core GEMM: Y[M,Nc] = X[M,K] @ W[Nc,K]^T + bias[Nc]
// 128x128 block tile, BK=16, 256 threads = 8 warps (2x4), warp tile 64x32.
// Loader: LDG.128 -> cvt.rna.tf32 (once) -> STS.128, register double-buffered
// across two smem stages, one __syncthreads per K-step.
// Inner loop: ldmatrix.x4.b16 + mma.sync.m16n8k8.
// FUSE variant: epilogue adds vp[src]+vp[dst] and accumulates BN stats into
// g_sum/g_sumsq (must be zeroed beforehand by the preceding finalize kernel).
// Requires: K % 16 == 0, Nc % 128 == 0. M arbitrary.
// ---------------------------------------------------------------------------
#define SM_STRIDE 20
#define TILE_FLOATS (128 * SM_STRIDE)
#define TILE_BYTES  (TILE_FLOATS * 4)

__device__ __forceinline__ uint32_t f2tf32(float f) {
    uint32_t u;
    asm("cvt.rna.tf32.f32 %0, %1;\n" : "=r"(u) : "f"(f));
    return u;
}
__device__ __forceinline__ void ldsm_x4(uint32_t& r0, uint32_t& r1,
                                        uint32_t& r2, uint32_t& r3, uint32_t addr) {
    asm volatile("ldmatrix.sync.aligned.m8n8.x4.shared.b16 {%0,%1,%2,%3}, [%4];\n"
                 : "=r"(r0), "=r"(r1), "=r"(r2), "=r"(r3) : "r"(addr));
}

template<bool FUSE>
__global__ __launch_bounds__(256)
void gemm_tf32(const float* __restrict__ X, const float* __restrict__ W,
               const float* __restrict__ bias, float* __restrict__ Y,
               int M, int Nc, int K,
               const float* __restrict__ vp, const int* __restrict__ src,
               const int* __restrict__ dst) {
    __shared__ float As[2][TILE_FLOATS];
    __shared__ float Bs[2][TILE_FLOATS];

    const int tid  = threadIdx.x;
    const int lane = tid & 31;
    const int warp = tid >> 5;
    const int wm   = (warp >> 2) * 64;   // warp row offset (0,64)
    const int wn   = (warp & 3) * 32;    // warp col offset (0,32,64,96)
    const int bm   = blockIdx.y * 128;
    const int bn   = blockIdx.x * 128;

    float acc[4][4][4];
#pragma unroll
    for (int i = 0; i < 4; i++)
#pragma unroll
        for (int j = 0; j < 4; j++)
#pragma unroll
            for (int c = 0; c < 4; c++) acc[i][j][c] = 0.0f;

    const int KT = K >> 4;   // BK = 16

    const int l_row0 = tid >> 2;              // 0..63
    const int l_row1 = (tid + 256) >> 2;      // 64..127
    const int l_c4   = (tid & 3) << 2;        // 0,4,8,12

    const uint32_t smA = (uint32_t)__cvta_generic_to_shared(&As[0][0]);
    const uint32_t smB = (uint32_t)__cvta_generic_to_shared(&Bs[0][0]);
    const uint32_t a_lane = ((wm + (lane & 15)) * SM_STRIDE + (lane >> 4) * 4) * 4;
    const uint32_t b_lane = ((wn + (lane >> 4) * 8 + (lane & 7)) * SM_STRIDE
                             + ((lane >> 3) & 1) * 4) * 4;

    float4 ra0, ra1, rb0, rb1;
    auto ldg_tile = [&](int kt) {
        const float4 z = make_float4(0.f, 0.f, 0.f, 0.f);
        int ar0 = bm + l_row0, ar1 = bm + l_row1;
        ra0 = (ar0 < M) ? *(const float4*)(X + (size_t)ar0 * K + kt * 16 + l_c4) : z;
        ra1 = (ar1 < M) ? *(const float4*)(X + (size_t)ar1 * K + kt * 16 + l_c4) : z;
        rb0 = *(const float4*)(W + (size_t)(bn + l_row0) * K + kt * 16 + l_c4);
        rb1 = *(const float4*)(W + (size_t)(bn + l_row1) * K + kt * 16 + l_c4);
    };
    auto sts_tile = [&](int buf) {
        uint4 ta0 = make_uint4(f2tf32(ra0.x), f2tf32(ra0.y), f2tf32(ra0.z), f2tf32(ra0.w));
        uint4 ta1 = make_uint4(f2tf32(ra1.x), f2tf32(ra1.y), f2tf32(ra1.z), f2tf32(ra1.w));
        uint4 tb0 = make_uint4(f2tf32(rb0.x), f2tf32(rb0.y), f2tf32(rb0.z), f2tf32(rb0.w));
        uint4 tb1 = make_uint4(f2tf32(rb1.x), f2tf32(rb1.y), f2tf32(rb1.z), f2tf32(rb1.w));
        *(uint4*)&As[buf][l_row0 * SM_STRIDE + l_c4] = ta0;
        *(uint4*)&As[buf][l_row1 * SM_STRIDE + l_c4] = ta1;
        *(uint4*)&Bs[buf][l_row0 * SM_STRIDE + l_c4] = tb0;
        *(uint4*)&Bs[buf][l_row1 * SM_STRIDE + l_c4] = tb1;
    };

    ldg_tile(0);
    sts_tile(0);

    for (int kt = 0; kt < KT; kt++) {
        __syncthreads();
        const int buf = kt & 1;
        if (kt + 1 < KT) ldg_tile(kt + 1);

        const uint32_t baseA = smA + buf * TILE_BYTES + a_lane;
        const uint32_t baseB = smB + buf * TILE_BYTES + b_lane;

#pragma unroll
        for (int ks = 0; ks < 2; ks++) {
            uint32_t a[4][4], bq[2][4];
#pragma unroll
            for (int mf = 0; mf < 4; mf++)
                ldsm_x4(a[mf][0], a[mf][1], a[mf][2], a[mf][3],
                        baseA + (mf * 16 * SM_STRIDE + ks * 8) * 4);
#pragma unroll
            for (int j = 0; j < 2; j++)
                ldsm_x4(bq[j][0], bq[j][1], bq[j][2], bq[j][3],
                        baseB + (j * 16 * SM_STRIDE + ks * 8) * 4);
#pragma unroll
            for (int mf = 0; mf < 4; mf++)
#pragma unroll
                for (int nf = 0; nf < 4; nf++) {
                    uint32_t b0 = bq[nf >> 1][(nf & 1) * 2 + 0];
                    uint32_t b1 = bq[nf >> 1][(nf & 1) * 2 + 1];
                    asm volatile(
                        "mma.sync.aligned.m16n8k8.row.col.f32.tf32.tf32.f32 "
                        "{%0,%1,%2,%3},{%4,%5,%6,%7},{%8,%9},{%0,%1,%2,%3};\n"
                        : "+f"(acc[mf][nf][0]), "+f"(acc[mf][nf][1]),
                          "+f"(acc[mf][nf][2]), "+f"(acc[mf][nf][3])
                        : "r"(a[mf][0]), "r"(a[mf][1]), "r"(a[mf][2]), "r"(a[mf][3]),
                          "r"(b0), "r"(b1));
                }
        }
        if (kt + 1 < KT) sts_tile(buf ^ 1);
    }

    // bias values for this thread's 8 columns
    float bv[4][2];
#pragma unroll
    for (int nf = 0; nf < 4; nf++) {
        int col = bn + wn + nf * 8 + (lane & 3) * 2;
        bv[nf][0] = bias[col];
        bv[nf][1] = bias[col + 1];
    }

    if (!FUSE) {
#pragma unroll
        for (int nf = 0; nf < 4; nf++) {
            int col = bn + wn + nf * 8 + (lane & 3) * 2;
#pragma unroll
            for (int mf = 0; mf < 4; mf++) {
                int row = bm + wm + mf * 16 + (lane >> 2);
                if (row < M) {
                    float2 o = make_float2(acc[mf][nf][0] + bv[nf][0],
                                           acc[mf][nf][1] + bv[nf][1]);
                    *(float2*)(Y + (size_t)row * Nc + col) = o;
                }
                if (row + 8 < M) {
                    float2 o = make_float2(acc[mf][nf][2] + bv[nf][0],
                                           acc[mf][nf][3] + bv[nf][1]);
                    *(float2*)(Y + (size_t)(row + 8) * Nc + col) = o;
                }
            }
        }
    } else {
        // Fused epilogue: t = acc + bias + vp[src] + vp[dst]; BN stats.
        float csum[8], csq[8];
#pragma unroll
        for (int i = 0; i < 8; i++) { csum[i] = 0.f; csq[i] = 0.f; }

#pragma unroll
        for (int mf = 0; mf < 4; mf++) {
#pragma unroll
            for (int half = 0; half < 2; half++) {
                int row = bm + wm + mf * 16 + (lane >> 2) + half * 8;
                if (row < M) {
                    int va = src[row], vb = dst[row];
                    const float* pa = vp + (size_t)va * 256;
                    const float* pb = vp + (size_t)vb * 256;
#pragma unroll
                    for (int nf = 0; nf < 4; nf++) {
                        int col = bn + wn + nf * 8 + (lane & 3) * 2;
                        float2 ga = *(const float2*)(pa + col);
                        float2 gb = *(const float2*)(pb + col);
                        float v0 = acc[mf][nf][half * 2 + 0] + bv[nf][0] + ga.x + gb.x;
                        float v1 = acc[mf][nf][half * 2 + 1] + bv[nf][1] + ga.y + gb.y;
                        *(float2*)(Y + (size_t)row * Nc + col) = make_float2(v0, v1);
                        csum[nf * 2 + 0] += v0;  csq[nf * 2 + 0] += v0 * v0;
                        csum[nf * 2 + 1] += v1;  csq[nf * 2 + 1] += v1 * v1;
                    }
                }
            }
        }
#pragma unroll
        for (int off = 16; off >= 4; off >>= 1) {
#pragma unroll
            for (int i = 0; i < 8; i++) {
                csum[i] += __shfl_xor_sync(0xFFFFFFFFu, csum[i], off);
                csq[i]  += __shfl_xor_sync(0xFFFFFFFFu, csq[i],  off);
            }
        }
        __syncthreads();               // done reading smem tiles; reuse for stats
        float* ssum = &As[0][0];       // [128]
        float* ssq  = &As[0][128];     // [128]
        if (tid < 128) { ssum[tid] = 0.f; ssq[tid] = 0.f; }
        __syncthreads();
        if (lane < 4) {
#pragma unroll
            for (int nf = 0; nf < 4; nf++) {
#pragma unroll
                for (int c = 0; c < 2; c++) {
                    int lcol = wn + nf * 8 + lane * 2 + c;   // 0..127
                    atomicAdd(&ssum[lcol], csum[nf * 2 + c]);
                    atomicAdd(&ssq[lcol],  csq[nf * 2 + c]);
                }
            }
        }
        __syncthreads();
        if (tid < 128) {
            atomicAdd(&g_sum[bn + tid],   ssum[tid]);
            atomicAdd(&g_sumsq[bn + tid], ssq[tid]);
        }
    }
}

// ---------------------------------------------------------------------------
// Finalize BN: scale/shift per channel (biased variance, eps=1e-5).
// Zeroes the stat accumulators afterwards for the NEXT fused stats pass.
// ---------------------------------------------------------------------------
__global__ void bn_finalize(const float* __restrict__ g, const float* __restrict__ b,
                            float inv_n) {
    int h = threadIdx.x;
    float mean = g_sum[h] * inv_n;
    float var = g_sumsq[h] * inv_n - mean * mean;
    float sc = g[h] * rsqrtf(var + 1e-5f);
    g_scale[h] = sc;
    g_shift[h] = b[h] - mean * sc;
    g_sum[h] = 0.0f;
    g_sumsq[h] = 0.0f;
}

// ---------------------------------------------------------------------------
// ep = relu(bn(t)); scatter-max into vie[src], vie[dst]; e_in += ep
// ---------------------------------------------------------------------------
__global__ void bn_relu_scatter(const float4* __restrict__ t, float4* __restrict__ ein,
                                float* __restrict__ vie, const int* __restrict__ src,
                                const int* __restrict__ dst, int E) {
    size_t total = (size_t)E * (H / 4);
    size_t stride = (size_t)gridDim.x * blockDim.x;
    for (size_t idx = (size_t)blockIdx.x * blockDim.x + threadIdx.x; idx < total;
         idx += stride) {
        int c4 = (int)(idx & 63);          // H/4 = 64
        int r  = (int)(idx >> 6);
        int h4 = c4 << 2;
        float4 tv = t[idx];
        float4 v;
        v.x = fmaxf(fmaf(tv.x, g_scale[h4 + 0], g_shift[h4 + 0]), 0.f);
        v.y = fmaxf(fmaf(tv.y, g_scale[h4 + 1], g_shift[h4 + 1]), 0.f);
        v.z = fmaxf(fmaf(tv.z, g_scale[h4 + 2], g_shift[h4 + 2]), 0.f);
        v.w = fmaxf(fmaf(tv.w, g_scale[h4 + 3], g_shift[h4 + 3]), 0.f);
        int a = src[r], b = dst[r];
        int* pa = (int*)&vie[(size_t)a * H + h4];
        int* pb = (int*)&vie[(size_t)b * H + h4];
        atomicMax(pa + 0, __float_as_int(v.x));
        atomicMax(pa + 1, __float_as_int(v.y));
        atomicMax(pa + 2, __float_as_int(v.z));
        atomicMax(pa + 3, __float_as_int(v.w));
        atomicMax(pb + 0, __float_as_int(v.x));
        atomicMax(pb + 1, __float_as_int(v.y));
        atomicMax(pb + 2, __float_as_int(v.z));
        atomicMax(pb + 3, __float_as_int(v.w));
        float4 e = ein[idx];
        e.x += v.x; e.y += v.y; e.z += v.z; e.w += v.w;
        ein[idx] = e;
    }
}

// ---------------------------------------------------------------------------
// GRU gate math + BN stats on h.
// ---------------------------------------------------------------------------
__global__ void gru_elem(const float* __restrict__ gi, const float* __restrict__ gh,
                         const float* __restrict__ vin, float* __restrict__ hbuf,
                         int N) {
    size_t total = (size_t)N * H;
    size_t stride = (size_t)gridDim.x * blockDim.x;   // multiple of 256
    int h = threadIdx.x & (H - 1);
    float s = 0.f, s2 = 0.f;
    bool any = false;
    for (size_t idx = (size_t)blockIdx.x * blockDim.x + threadIdx.x; idx < total;
         idx += stride) {
        int n = (int)(idx >> 8);
        const float* giR = gi + (size_t)n * (3 * H);
        const float* ghR = gh + (size_t)n * (3 * H);
        float ir = giR[h], iz = giR[h + H], ig = giR[h + 2 * H];
        float hr = ghR[h], hz = ghR[h + H], hg = ghR[h + 2 * H];
        float r = 1.0f / (1.0f + expf(-(ir + hr)));
        float z = 1.0f / (1.0f + expf(-(iz + hz)));
        float nn = tanhf(ig + r * hg);
        float hv = (1.0f - z) * nn + z * vin[idx];
        hbuf[idx] = hv;
        s += hv;
        s2 += hv * hv;
        any = true;
    }
    if (any) {
        atomicAdd(&g_sum[h], s);
        atomicAdd(&g_sumsq[h], s2);
    }
}

// ---------------------------------------------------------------------------
// v_in += relu(bn(hbuf))
// ---------------------------------------------------------------------------
__global__ void v_update(float* __restrict__ vin, const float* __restrict__ hbuf,
                         int total) {
    int stride = gridDim.x * blockDim.x;
    for (int idx = blockIdx.x * blockDim.x + threadIdx.x; idx < total; idx += stride) {
        int h = idx & (H - 1);
        float v = fmaf(hbuf[idx], g_scale[h], g_shift[h]);
        vin[idx] += fmaxf(v, 0.0f);
    }
}

// ---------------------------------------------------------------------------
// out[e] = dot(e_in[e], w_comb) + b_comb   (one warp per edge)
// ---------------------------------------------------------------------------
__global__ void final_out(const float* __restrict__ ein, float* __restrict__ out,
                          int E) {
    int warp = (blockIdx.x * blockDim.x + threadIdx.x) >> 5;
    int lane = threadIdx.x & 31;
    if (warp >= E) return;
    const float* row = ein + (size_t)warp * H;
    float s = 0.f;
#pragma unroll
    for (int j = 0; j < 8; j++) {
        int c = j * 32 + lane;
        s = fmaf(row[c], g_wcomb[c], s);
    }
#pragma unroll
    for (int o = 16; o > 0; o >>= 1) s += __shfl_xor_sync(0xFFFFFFFFu, s, o);
    if (lane == 0) out[warp] = s + g_bcomb[0];
}

// ---------------------------------------------------------------------------
// Launch — dual-stream fork/join inside graph capture.
// Side stream runs: node encoder, vie zeroing, and the gh GEMM (vin @ whh),
// all off the critical path. Events create the capture dependencies.
// Streams/events are created fresh each call (kernel_launch runs only a few
// times; replays replay the captured graph, not this function).
// ---------------------------------------------------------------------------
extern "C" void kernel_launch(void* const* d_in, const int* in_sizes, int n_in,
                              void* d_out, int out_size) {
    const float* x         = (const float*)d_in[0];
    const float* edge_attr = (const float*)d_in[1];
    const int*   edge_idx  = (const int*)  d_in[2];
    const float* ew        = (const float*)d_in[3];
    const float* eb        = (const float*)d_in[4];
    const float* vw        = (const float*)d_in[5];
    const float* vb        = (const float*)d_in[6];
    const float* Le_w      = (const float*)d_in[7];
    const float* Le_b      = (const float*)d_in[8];
    const float* Lv_w      = (const float*)d_in[9];
    const float* Lv_b      = (const float*)d_in[10];
    const float* bne_g     = (const float*)d_in[11];
    const float* bne_b     = (const float*)d_in[12];
    const float* bnv_g     = (const float*)d_in[13];
    const float* bnv_b     = (const float*)d_in[14];
    const float* gru_wih   = (const float*)d_in[15];
    const float* gru_whh   = (const float*)d_in[16];
    const float* gru_bih   = (const float*)d_in[17];
    const float* gru_bhh   = (const float*)d_in[18];
    const float* fin_w     = (const float*)d_in[19];
    const float* fin_b     = (const float*)d_in[20];
    const float* out_w     = (const float*)d_in[21];
    const float* out_b     = (const float*)d_in[22];
    float* out = (float*)d_out;

    const int E = in_sizes[1] / FE;
    const int N = in_sizes[0] / FV;
    const int* src = edge_idx;
    const int* dst = edge_idx + E;

    float *p_ein, *p_t, *p_vin, *p_vp, *p_vie, *p_gi, *p_gh, *p_hbuf;
    cudaGetSymbolAddress((void**)&p_ein,  g_ein);
    cudaGetSymbolAddress((void**)&p_t,    g_t);
    cudaGetSymbolAddress((void**)&p_vin,  g_vin);
    cudaGetSymbolAddress((void**)&p_vp,   g_vp);
    cudaGetSymbolAddress((void**)&p_vie,  g_vie);
    cudaGetSymbolAddress((void**)&p_gi,   g_gi);
    cudaGetSymbolAddress((void**)&p_gh,   g_gh);
    cudaGetSymbolAddress((void**)&p_hbuf, g_hbuf);

    const int nbE = (E + 127) / 128;   // 2500
    const int nbN = (N + 127) / 128;   // 157

    // side stream + events (created per call; leaked — only ~2 calls total)
    cudaStream_t s2;
    cudaStreamCreateWithFlags(&s2, cudaStreamNonBlocking);
    cudaEvent_t evFork, evVZ[NL], evGH[NL], evVU[NL], evGI[NL];
    cudaEventCreateWithFlags(&evFork, cudaEventDisableTiming);
    for (int k = 0; k < NL; k++) {
        cudaEventCreateWithFlags(&evVZ[k], cudaEventDisableTiming);
        cudaEventCreateWithFlags(&evGH[k], cudaEventDisableTiming);
        cudaEventCreateWithFlags(&evVU[k], cudaEventDisableTiming);
        cudaEventCreateWithFlags(&evGI[k], cudaEventDisableTiming);
    }

    // main: fold fin/out tail; zero stats for first fused edge-stats pass
    combine_final<<<1, H>>>(fin_w, fin_b, out_w, out_b);

    // fork side stream
    cudaEventRecord(evFork, 0);
    cudaStreamWaitEvent(s2, evFork, 0);

    // s2: node encoder -> zero vie(0)
    gemm_tf32<false><<<dim3(H / 128, nbN), 256, 0, s2>>>(
        x, vw, vb, p_vin, N, H, FV, nullptr, nullptr, nullptr);
    zero_k<<<(N * H + 255) / 256, 256, 0, s2>>>(p_vie, N * H);
    cudaEventRecord(evVZ[0], s2);

    // main: edge encoder (concurrent with node encoder)
    gemm_tf32<false><<<dim3(H / 128, nbE), 256>>>(
        edge_attr, ew, eb, p_ein, E, H, FE, nullptr, nullptr, nullptr);

    // main needs vin (and vie zeroed) before Lv(0)/scatter(0)
    cudaStreamWaitEvent(0, evVZ[0], 0);

    for (int k = 0; k < NL; k++) {
        // s2: gh = vin @ whh^T + bhh (vin ready: k==0 via s2 order, else evVU)
        if (k > 0) cudaStreamWaitEvent(s2, evVU[k - 1], 0);
        gemm_tf32<false><<<dim3(3 * H / 128, nbN), 256, 0, s2>>>(
            p_vin, gru_whh + (size_t)k * 3 * H * H, gru_bhh + (size_t)k * 3 * H,
            p_gh, N, 3 * H, H, nullptr, nullptr, nullptr);
        cudaEventRecord(evGH[k], s2);
        // s2: zero vie for layer k (k>0: after gi(k-1) consumed it)
        if (k > 0) {
            cudaStreamWaitEvent(s2, evGI[k - 1], 0);
            zero_k<<<(N * H + 255) / 256, 256, 0, s2>>>(p_vie, N * H);
            cudaEventRecord(evVZ[k], s2);
        }

        // main: vp = v_in @ Lv_w^T + Lv_b
        gemm_tf32<false><<<dim3(H / 128, nbN), 256>>>(
            p_vin, Lv_w + (size_t)k * H * H, Lv_b + k * H, p_vp, N, H, H,
            nullptr, nullptr, nullptr);

        // main: t = e_in @ Le_w^T + Le_b + vp[src] + vp[dst]  (+ BN stats)
        gemm_tf32<true><<<dim3(H / 128, nbE), 256>>>(
            p_ein, Le_w + (size_t)k * H * H, Le_b + k * H, p_t, E, H, H,
            p_vp, src, dst);
        bn_finalize<<<1, H>>>(bne_g + k * H, bne_b + k * H, 1.0f / (float)E);

        // main: scatter-max + e_in residual (vie zeroed on s2)
        cudaStreamWaitEvent(0, evVZ[k], 0);
        bn_relu_scatter<<<4096, 256>>>((const float4*)p_t, (float4*)p_ein, p_vie,
                                       src, dst, E);

        // main: gi = vie @ wih^T + bih
        gemm_tf32<false><<<dim3(3 * H / 128, nbN), 256>>>(
            p_vie, gru_wih + (size_t)k * 3 * H * H, gru_bih + (size_t)k * 3 * H,
            p_gi, N, 3 * H, H, nullptr, nullptr, nullptr);
        cudaEventRecord(evGI[k], 0);

        // main: GRU gate math (needs gh from s2)
        cudaStreamWaitEvent(0, evGH[k], 0);
        gru_elem<<<512, 256>>>(p_gi, p_gh, p_vin, p_hbuf, N);
        bn_finalize<<<1, H>>>(bnv_g + k * H, bnv_b + k * H, 1.0f / (float)N);
        v_update<<<2048, 256>>>(p_vin, p_hbuf, N * H);
        cudaEventRecord(evVU[k], 0);
    }

    // out[e] = dot(e_in[e], w_comb) + b_comb
    final_out<<<(E * 32 + 255) / 256, 256>>>(p_ein, out, E);
}